// round 1
// baseline (speedup 1.0000x reference)
#include <cuda_runtime.h>
#include <math.h>

// ---------------------------------------------------------------------------
// Shapes (fixed by the problem)
// ---------------------------------------------------------------------------
constexpr int B_    = 4;
constexpr int T_    = 2048;
constexpr int D_    = 1024;
constexpr int NH_   = 16;
constexpr int HC_   = 64;
constexpr int NTOK_ = B_ * T_;      // 8192
constexpr int PADW  = 68;           // shared-row pad (16B-aligned rows, conflict shift)

// ---------------------------------------------------------------------------
// Scratch (device globals — no runtime allocation allowed)
// ---------------------------------------------------------------------------
__device__ float g_Q  [(size_t)NTOK_ * D_];
__device__ float g_K  [(size_t)NTOK_ * D_];
__device__ float g_V  [(size_t)NTOK_ * D_];
__device__ float g_M  [(size_t)NTOK_ * D_];   // (1-w)*attn + w*P@V, pre-projection
__device__ float g_PRE[(size_t)NTOK_ * D_];   // prefix sums of V along t
__device__ float g_f[NH_][101];               // f_h(L), L = 0..100
__device__ float g_w;                         // sigmoid(mu)

// ---------------------------------------------------------------------------
// Setup: blend weight + positional decay table f_h(L)
// ---------------------------------------------------------------------------
__global__ void setup_kernel(const float* __restrict__ mu,
                             const float* __restrict__ lam,
                             const float* __restrict__ g1,
                             const float* __restrict__ g2,
                             const float* __restrict__ t1,
                             const float* __restrict__ t2)
{
    int tid = threadIdx.x;
    if (tid == 0) g_w = 1.f / (1.f + expf(-mu[0]));
    for (int idx = tid; idx < NH_ * 101; idx += blockDim.x) {
        int h = idx / 101, L = idx % 101;
        float Lf = (float)L;
        float val;
        if (h < 4) {                                  // retention heads (signed base)
            float base = lam[h];
            float mag  = expf(Lf * logf(fabsf(base)));
            float sgn  = (base < 0.f) ? (1.f - 2.f * (float)(L & 1)) : 1.f;
            val = mag * sgn;
        } else if (h < 10) {                          // C1 heads: gamma^L * sin(theta*L)
            int s = h - 4;
            val = expf(Lf * logf(g1[s])) * sinf(t1[s] * Lf);
        } else {                                      // C2 heads: gamma^L * cos(theta*L)
            int s = h - 10;
            val = expf(Lf * logf(g2[s])) * cosf(t2[s] * Lf);
        }
        g_f[h][L] = val;
    }
}

// ---------------------------------------------------------------------------
// NT GEMM with bias: C[m,n] = sum_k A[m,k]*W[n,k] + bias[n]
// A: [8192,1024], W: [1024,1024], 64x64 tile, 256 thr, 4x4 microtile
// ---------------------------------------------------------------------------
__global__ void __launch_bounds__(256)
gemm_nt_bias(const float* __restrict__ A, const float* __restrict__ W,
             const float* __restrict__ bias, float* __restrict__ C)
{
    __shared__ float As[16 * PADW];   // As[k][m]
    __shared__ float Bs[16 * PADW];   // Bs[k][n]
    const int tid = threadIdx.x;
    const int tx = tid & 15, ty = tid >> 4;
    const int lr = tid >> 2, lk = tid & 3;
    const int m0 = blockIdx.x * 64;
    const int n0 = blockIdx.y * 64;

    const float* Ap = A + (size_t)(m0 + lr) * D_ + lk * 4;
    const float* Wp = W + (size_t)(n0 + lr) * D_ + lk * 4;

    float acc[4][4] = {};
    for (int k0 = 0; k0 < D_; k0 += 16) {
        float4 a = *(const float4*)(Ap + k0);
        float4 b = *(const float4*)(Wp + k0);
        As[(lk*4+0)*PADW + lr] = a.x;
        As[(lk*4+1)*PADW + lr] = a.y;
        As[(lk*4+2)*PADW + lr] = a.z;
        As[(lk*4+3)*PADW + lr] = a.w;
        Bs[(lk*4+0)*PADW + lr] = b.x;
        Bs[(lk*4+1)*PADW + lr] = b.y;
        Bs[(lk*4+2)*PADW + lr] = b.z;
        Bs[(lk*4+3)*PADW + lr] = b.w;
        __syncthreads();
#pragma unroll
        for (int kk = 0; kk < 16; kk++) {
            float4 av = *(const float4*)(As + kk*PADW + ty*4);
            float4 bv = *(const float4*)(Bs + kk*PADW + tx*4);
            float aa[4] = {av.x, av.y, av.z, av.w};
            float bb[4] = {bv.x, bv.y, bv.z, bv.w};
#pragma unroll
            for (int i = 0; i < 4; i++)
#pragma unroll
                for (int j = 0; j < 4; j++)
                    acc[i][j] += aa[i] * bb[j];
        }
        __syncthreads();
    }
#pragma unroll
    for (int i = 0; i < 4; i++) {
        size_t row = (size_t)(m0 + ty*4 + i) * D_;
#pragma unroll
        for (int j = 0; j < 4; j++) {
            int n = n0 + tx*4 + j;
            C[row + n] = acc[i][j] + bias[n];
        }
    }
}

// ---------------------------------------------------------------------------
// Prefix sums of V along t (per (b, channel))
// ---------------------------------------------------------------------------
__global__ void prefix_kernel(const float* __restrict__ V, float* __restrict__ P)
{
    int idx = blockIdx.x * blockDim.x + threadIdx.x;   // 0..4095
    int b = idx >> 10, d = idx & 1023;
    size_t base = (size_t)(b * T_) * D_ + d;
    float s = 0.f;
#pragma unroll 4
    for (int t = 0; t < T_; t++) {
        s += V[base + (size_t)t * D_];
        P[base + (size_t)t * D_] = s;
    }
}

// ---------------------------------------------------------------------------
// 16-lane warp-group reductions (lanes differ in bits 0..3 only)
// ---------------------------------------------------------------------------
__device__ __forceinline__ float rmax16(float v) {
#pragma unroll
    for (int off = 1; off < 16; off <<= 1)
        v = fmaxf(v, __shfl_xor_sync(0xffffffffu, v, off));
    return v;
}
__device__ __forceinline__ float rsum16(float v) {
#pragma unroll
    for (int off = 1; off < 16; off <<= 1)
        v += __shfl_xor_sync(0xffffffffu, v, off);
    return v;
}

// ---------------------------------------------------------------------------
// Flash attention (full, NON-causal softmax), writes (1-w)*attn@V into M
// One block per (b, h, 64-row q tile); 256 threads, 4x4 microtiles
// ---------------------------------------------------------------------------
__global__ void __launch_bounds__(256)
attn_kernel(const float* __restrict__ Q, const float* __restrict__ K,
            const float* __restrict__ V, float* __restrict__ M)
{
    extern __shared__ float sm[];
    float* Qs  = sm;                 // [64][PADW]  Qs[d][q]
    float* KWs = sm + 64 * PADW;     // Ks[d][k] then reused as Ws[k][q]
    float* Vs  = sm + 2 * 64 * PADW; // Vs[k][d]

    const int b = blockIdx.z, h = blockIdx.y;
    const int q0 = blockIdx.x * 64;
    const int tid = threadIdx.x;
    const int tx = tid & 15, ty = tid >> 4;
    const int lr = tid >> 2, lc = tid & 3;

    // load Q tile transposed: Qs[d][q]
    const float* Qg = Q + ((size_t)(b * T_) + q0 + lr) * D_ + h * HC_;
#pragma unroll
    for (int u = 0; u < 4; u++) {
        int c4 = lc + u * 4;
        float4 g = *(const float4*)(Qg + c4 * 4);
        Qs[(c4*4+0)*PADW + lr] = g.x;
        Qs[(c4*4+1)*PADW + lr] = g.y;
        Qs[(c4*4+2)*PADW + lr] = g.z;
        Qs[(c4*4+3)*PADW + lr] = g.w;
    }

    float acc[4][4] = {};
    float mrow[4] = {-1e30f, -1e30f, -1e30f, -1e30f};
    float lrow[4] = {0.f, 0.f, 0.f, 0.f};

    for (int k0 = 0; k0 < T_; k0 += 64) {
        const float* Kg = K + ((size_t)(b * T_) + k0 + lr) * D_ + h * HC_;
        const float* Vg = V + ((size_t)(b * T_) + k0 + lr) * D_ + h * HC_;
#pragma unroll
        for (int u = 0; u < 4; u++) {
            int c4 = lc + u * 4;
            float4 gk = *(const float4*)(Kg + c4 * 4);
            KWs[(c4*4+0)*PADW + lr] = gk.x;
            KWs[(c4*4+1)*PADW + lr] = gk.y;
            KWs[(c4*4+2)*PADW + lr] = gk.z;
            KWs[(c4*4+3)*PADW + lr] = gk.w;
            float4 gv = *(const float4*)(Vg + c4 * 4);
            *(float4*)(Vs + lr * PADW + c4 * 4) = gv;
        }
        __syncthreads();

        // S = Q K^T  (s[i][j]: q = ty*4+i, k = tx*4+j)
        float s[4][4] = {};
#pragma unroll
        for (int d = 0; d < 64; d++) {
            float4 av = *(const float4*)(Qs  + d*PADW + ty*4);
            float4 bv = *(const float4*)(KWs + d*PADW + tx*4);
            float aa[4] = {av.x, av.y, av.z, av.w};
            float bb[4] = {bv.x, bv.y, bv.z, bv.w};
#pragma unroll
            for (int i = 0; i < 4; i++)
#pragma unroll
                for (int j = 0; j < 4; j++)
                    s[i][j] += aa[i] * bb[j];
        }
        __syncthreads();   // everyone done reading K tile -> reuse as W tile

        // online softmax
#pragma unroll
        for (int i = 0; i < 4; i++) {
            float mt = fmaxf(fmaxf(s[i][0], s[i][1]), fmaxf(s[i][2], s[i][3]));
            mt = rmax16(mt);
            float mnew = fmaxf(mrow[i], mt);
            float rs = 0.f;
#pragma unroll
            for (int j = 0; j < 4; j++) {
                float p = __expf(s[i][j] - mnew);
                s[i][j] = p;
                rs += p;
            }
            rs = rsum16(rs);
            float sc = __expf(mrow[i] - mnew);
            lrow[i] = lrow[i] * sc + rs;
            mrow[i] = mnew;
#pragma unroll
            for (int j = 0; j < 4; j++) acc[i][j] *= sc;
        }

        // Ws[k][q] = exp weights (transposed for the V matmul)
#pragma unroll
        for (int j = 0; j < 4; j++)
#pragma unroll
            for (int i = 0; i < 4; i++)
                KWs[(tx*4+j)*PADW + ty*4+i] = s[i][j];
        __syncthreads();

        // acc += Ws * Vs
#pragma unroll
        for (int k = 0; k < 64; k++) {
            float4 av = *(const float4*)(KWs + k*PADW + ty*4);
            float4 vv = *(const float4*)(Vs  + k*PADW + tx*4);
            float aa[4] = {av.x, av.y, av.z, av.w};
            float bb[4] = {vv.x, vv.y, vv.z, vv.w};
#pragma unroll
            for (int i = 0; i < 4; i++)
#pragma unroll
                for (int j = 0; j < 4; j++)
                    acc[i][j] += aa[i] * bb[j];
        }
        __syncthreads();
    }

    const float wb = g_w;
#pragma unroll
    for (int i = 0; i < 4; i++) {
        float inv = (1.f - wb) / lrow[i];
        size_t row = ((size_t)(b * T_) + q0 + ty*4 + i) * D_ + h * HC_;
#pragma unroll
        for (int j = 0; j < 4; j++)
            M[row + tx*4 + j] = acc[i][j] * inv;
    }
}

// ---------------------------------------------------------------------------
// P@V via window-99 causal conv + f(100)*prefix.  M += w * (P@V)
// P[h,i,j] = f_h(min(i-j,100)) for j<i:
//   P@V[i] = sum_{d=1..min(i,99)} f(d) V[i-d]  +  f(100) * PRE[i-100]  (i>=100)
// ---------------------------------------------------------------------------
__global__ void pwin_kernel(const float* __restrict__ V,
                            const float* __restrict__ PRE,
                            float* __restrict__ M)
{
    int c = threadIdx.x;                               // 0..63 channel in head
    int t = blockIdx.x * blockDim.y + threadIdx.y;     // token
    int h = blockIdx.y, b = blockIdx.z;
    const float* f = g_f[h];
    size_t colbase = (size_t)(b * T_) * D_ + (size_t)h * HC_ + c;

    float acc = 0.f;
    int dmax = min(t, 99);
    for (int d = 1; d <= dmax; d++)
        acc += f[d] * V[colbase + (size_t)(t - d) * D_];
    if (t >= 100)
        acc += f[100] * PRE[colbase + (size_t)(t - 100) * D_];

    M[colbase + (size_t)t * D_] += g_w * acc;
}

// ---------------------------------------------------------------------------
// Launch
// ---------------------------------------------------------------------------
extern "C" void kernel_launch(void* const* d_in, const int* in_sizes, int n_in,
                              void* d_out, int out_size)
{
    const float* x   = (const float*)d_in[0];
    const float* mu  = (const float*)d_in[1];
    const float* lam = (const float*)d_in[2];
    const float* g1  = (const float*)d_in[3];
    const float* g2  = (const float*)d_in[4];
    const float* t1  = (const float*)d_in[5];
    const float* t2  = (const float*)d_in[6];
    const float* Wq  = (const float*)d_in[7];
    const float* bq  = (const float*)d_in[8];
    const float* Wk  = (const float*)d_in[9];
    const float* bk  = (const float*)d_in[10];
    const float* Wv  = (const float*)d_in[11];
    const float* bv  = (const float*)d_in[12];
    const float* Wf  = (const float*)d_in[13];
    const float* bf  = (const float*)d_in[14];
    float* out = (float*)d_out;

    float *Qb, *Kb, *Vb, *Mb, *PREb;
    cudaGetSymbolAddress((void**)&Qb,   g_Q);
    cudaGetSymbolAddress((void**)&Kb,   g_K);
    cudaGetSymbolAddress((void**)&Vb,   g_V);
    cudaGetSymbolAddress((void**)&Mb,   g_M);
    cudaGetSymbolAddress((void**)&PREb, g_PRE);

    const int attn_smem = 3 * 64 * PADW * 4;   // 52224 B > 48KB -> opt in
    cudaFuncSetAttribute(attn_kernel,
                         cudaFuncAttributeMaxDynamicSharedMemorySize, attn_smem);

    setup_kernel<<<1, 128>>>(mu, lam, g1, g2, t1, t2);

    dim3 ggrid(NTOK_ / 64, D_ / 64);
    gemm_nt_bias<<<ggrid, 256>>>(x, Wq, bq, Qb);
    gemm_nt_bias<<<ggrid, 256>>>(x, Wk, bk, Kb);
    gemm_nt_bias<<<ggrid, 256>>>(x, Wv, bv, Vb);

    prefix_kernel<<<16, 256>>>(Vb, PREb);

    dim3 agrid(T_ / 64, NH_, B_);
    attn_kernel<<<agrid, 256, attn_smem>>>(Qb, Kb, Vb, Mb);

    dim3 pblock(64, 4);
    dim3 pgrid(T_ / 4, NH_, B_);
    pwin_kernel<<<pgrid, pblock>>>(Vb, PREb, Mb);

    gemm_nt_bias<<<ggrid, 256>>>(Mb, Wf, bf, out);
}

// round 3
// speedup vs baseline: 2.3055x; 2.3055x over previous
#include <cuda_runtime.h>
#include <cuda_bf16.h>
#include <math.h>
#include <cstdint>

using bf16 = __nv_bfloat16;

// ---------------------------------------------------------------------------
// Shapes
// ---------------------------------------------------------------------------
constexpr int B_    = 4;
constexpr int T_    = 2048;
constexpr int D_    = 1024;
constexpr int NH_   = 16;
constexpr int HC_   = 64;
constexpr int NTOK_ = B_ * T_;      // 8192

// ---------------------------------------------------------------------------
// Scratch (device globals)
// ---------------------------------------------------------------------------
__device__ float g_V  [(size_t)NTOK_ * D_];
__device__ float g_M  [(size_t)NTOK_ * D_];
__device__ float g_PRE[(size_t)NTOK_ * D_];
__device__ float g_f[NH_][101];
__device__ float g_w;

__device__ bf16 g_xh[(size_t)NTOK_ * D_];
__device__ bf16 g_xl[(size_t)NTOK_ * D_];
__device__ bf16 g_Mh[(size_t)NTOK_ * D_];
__device__ bf16 g_Ml[(size_t)NTOK_ * D_];
__device__ bf16 g_Wh[4][(size_t)D_ * D_];
__device__ bf16 g_Wl[4][(size_t)D_ * D_];
__device__ bf16 g_Qh[(size_t)NTOK_ * D_];
__device__ bf16 g_Ql[(size_t)NTOK_ * D_];
__device__ bf16 g_Kh[(size_t)NTOK_ * D_];
__device__ bf16 g_Kl[(size_t)NTOK_ * D_];
__device__ bf16 g_Vh[(size_t)NTOK_ * D_];
__device__ bf16 g_Vl[(size_t)NTOK_ * D_];

// ---------------------------------------------------------------------------
// PTX helpers (plain sm_80-era PTX: valid on sm_103 non-'a' target)
// ---------------------------------------------------------------------------
__device__ __forceinline__ uint32_t smem_u32(const void* p) {
    uint32_t a;
    asm("{ .reg .u64 t; cvta.to.shared.u64 t, %1; cvt.u32.u64 %0, t; }"
        : "=r"(a) : "l"(p));
    return a;
}
#define CP16(s, g) \
    asm volatile("cp.async.cg.shared.global [%0], [%1], 16;" \
                 :: "r"(s), "l"(g) : "memory")
#define CP_COMMIT() asm volatile("cp.async.commit_group;" ::: "memory")
#define CP_WAIT(n)  asm volatile("cp.async.wait_group %0;" :: "n"(n) : "memory")

__device__ __forceinline__ void ldsm4(uint32_t& r0, uint32_t& r1,
                                      uint32_t& r2, uint32_t& r3, uint32_t a) {
    asm volatile("ldmatrix.sync.aligned.m8n8.x4.shared.b16 {%0,%1,%2,%3}, [%4];"
                 : "=r"(r0), "=r"(r1), "=r"(r2), "=r"(r3) : "r"(a));
}
__device__ __forceinline__ void ldsm4t(uint32_t& r0, uint32_t& r1,
                                       uint32_t& r2, uint32_t& r3, uint32_t a) {
    asm volatile("ldmatrix.sync.aligned.m8n8.x4.trans.shared.b16 {%0,%1,%2,%3}, [%4];"
                 : "=r"(r0), "=r"(r1), "=r"(r2), "=r"(r3) : "r"(a));
}
__device__ __forceinline__ void mma16816(float* c, const uint32_t* a, const uint32_t* b) {
    asm volatile(
        "mma.sync.aligned.m16n8k16.row.col.f32.bf16.bf16.f32 "
        "{%0,%1,%2,%3},{%4,%5,%6,%7},{%8,%9},{%0,%1,%2,%3};"
        : "+f"(c[0]), "+f"(c[1]), "+f"(c[2]), "+f"(c[3])
        : "r"(a[0]), "r"(a[1]), "r"(a[2]), "r"(a[3]), "r"(b[0]), "r"(b[1]));
}
// pack {lo -> low half, hi -> high half} as bf16x2 (round-to-nearest)
__device__ __forceinline__ uint32_t packbf(float lo, float hi) {
    uint32_t r;
    asm("cvt.rn.bf16x2.f32 %0, %1, %2;" : "=r"(r) : "f"(hi), "f"(lo));
    return r;
}

// ---------------------------------------------------------------------------
// fp32 -> bf16 (hi, lo) split
// ---------------------------------------------------------------------------
__global__ void split_kernel(const float* __restrict__ s,
                             bf16* __restrict__ hi, bf16* __restrict__ lo, int n4)
{
    int i = blockIdx.x * blockDim.x + threadIdx.x;
    if (i >= n4) return;
    float4 a = ((const float4*)s)[i];
    float h0 = __bfloat162float(__float2bfloat16_rn(a.x));
    float h1 = __bfloat162float(__float2bfloat16_rn(a.y));
    float h2 = __bfloat162float(__float2bfloat16_rn(a.z));
    float h3 = __bfloat162float(__float2bfloat16_rn(a.w));
    uint2 H, L;
    H.x = packbf(a.x, a.y);          H.y = packbf(a.z, a.w);
    L.x = packbf(a.x - h0, a.y - h1); L.y = packbf(a.z - h2, a.w - h3);
    ((uint2*)hi)[i] = H;
    ((uint2*)lo)[i] = L;
}

// ---------------------------------------------------------------------------
// HMMA NT GEMM, bf16x3 split:  C[m,n] = sum_k A[m,k] W[n,k] + bias[n]
// CTA 128x128, BK=32, 8 warps (2m x 4n), warp tile 64x32, cp.async double buf
// SMEM tile: [128][40] bf16 (80B row stride -> conflict-free ldmatrix)
// ---------------------------------------------------------------------------
constexpr int GL  = 40;                    // smem row stride (elems)
constexpr int GTB = 128 * GL * 2;          // 10240 B per tile
constexpr int GBUF = 4 * GTB;              // Ah,Al,Bh,Bl
constexpr int GSMEM = 2 * GBUF;            // 81920 B

__global__ void __launch_bounds__(256)
tc_gemm(const bf16* __restrict__ Ah, const bf16* __restrict__ Al,
        const bf16* __restrict__ Bh, const bf16* __restrict__ Bl,
        const float* __restrict__ bias,
        float* __restrict__ Cf, bf16* __restrict__ Ch, bf16* __restrict__ Cl)
{
    extern __shared__ char sm[];
    const uint32_t su = smem_u32(sm);
    const int tid = threadIdx.x;
    const int wid = tid >> 5, lane = tid & 31;
    const int wm = wid & 1, wn = wid >> 1;
    const int m0 = blockIdx.x * 128, n0 = blockIdx.y * 128;

    const bf16* srcs[4] = { Ah + (size_t)m0 * D_, Al + (size_t)m0 * D_,
                            Bh + (size_t)n0 * D_, Bl + (size_t)n0 * D_ };

    const int lrow = lane & 15, lcol8 = (lane >> 4) * 8;
    const int g = lane >> 2, tg = lane & 3;

    // chunk loader
    auto load_chunk = [&](int c, int buf) {
        const int k0 = c * 32;
#pragma unroll
        for (int t = 0; t < 4; t++)
#pragma unroll
            for (int r = 0; r < 2; r++) {
                int id = r * 256 + tid;
                int row = id >> 2, q = id & 3;
                CP16(su + buf * GBUF + t * GTB + row * 80 + q * 16,
                     srcs[t] + (size_t)row * D_ + k0 + q * 8);
            }
    };

    load_chunk(0, 0); CP_COMMIT();

    float acc[4][4][4] = {};

    for (int c = 0; c < 32; c++) {
        if (c < 31) { load_chunk(c + 1, (c + 1) & 1); CP_COMMIT(); CP_WAIT(1); }
        else        { CP_WAIT(0); }
        __syncthreads();
        const uint32_t base = su + (c & 1) * GBUF;
        const int kk = 0;  // BK=32 handled as 2 k16 below
#pragma unroll
        for (int k2 = 0; k2 < 2; k2++) {
            const int kc = (kk + k2) * 16 + lcol8;
            uint32_t ah[4][4], al[4][4];
#pragma unroll
            for (int mt = 0; mt < 4; mt++) {
                uint32_t ar = base + ((wm * 64 + mt * 16 + lrow) * GL + kc) * 2;
                ldsm4(ah[mt][0], ah[mt][1], ah[mt][2], ah[mt][3], ar);
                ldsm4(al[mt][0], al[mt][1], al[mt][2], al[mt][3], ar + GTB);
            }
            uint32_t bh[4][2], bl[4][2];
#pragma unroll
            for (int np = 0; np < 2; np++) {
                uint32_t br = base + 2 * GTB + ((wn * 32 + np * 16 + lrow) * GL + kc) * 2;
                uint32_t r0, r1, r2, r3;
                ldsm4(r0, r1, r2, r3, br);
                bh[2*np][0] = r0; bh[2*np][1] = r2;
                bh[2*np+1][0] = r1; bh[2*np+1][1] = r3;
                ldsm4(r0, r1, r2, r3, br + GTB);
                bl[2*np][0] = r0; bl[2*np][1] = r2;
                bl[2*np+1][0] = r1; bl[2*np+1][1] = r3;
            }
#pragma unroll
            for (int mt = 0; mt < 4; mt++)
#pragma unroll
                for (int nt = 0; nt < 4; nt++) {
                    mma16816(acc[mt][nt], ah[mt], bh[nt]);
                    mma16816(acc[mt][nt], ah[mt], bl[nt]);
                    mma16816(acc[mt][nt], al[mt], bh[nt]);
                }
        }
        __syncthreads();
    }

    // epilogue
#pragma unroll
    for (int mt = 0; mt < 4; mt++)
#pragma unroll
        for (int nt = 0; nt < 4; nt++) {
            const int col = n0 + wn * 32 + nt * 8 + tg * 2;
            const float b0v = bias[col], b1v = bias[col + 1];
#pragma unroll
            for (int hf = 0; hf < 2; hf++) {
                const int row = m0 + wm * 64 + mt * 16 + g + hf * 8;
                float v0 = acc[mt][nt][hf * 2]     + b0v;
                float v1 = acc[mt][nt][hf * 2 + 1] + b1v;
                if (Cf) {
                    float2 o; o.x = v0; o.y = v1;
                    *(float2*)(Cf + (size_t)row * D_ + col) = o;
                }
                if (Ch) {
                    float h0 = __bfloat162float(__float2bfloat16_rn(v0));
                    float h1 = __bfloat162float(__float2bfloat16_rn(v1));
                    *(uint32_t*)(Ch + (size_t)row * D_ + col) = packbf(v0, v1);
                    *(uint32_t*)(Cl + (size_t)row * D_ + col) = packbf(v0 - h0, v1 - h1);
                }
            }
        }
}

// ---------------------------------------------------------------------------
// HMMA flash attention, bf16x3 split on QK^T and on P.V
// CTA: 128 q-rows, 256 thr (8 warps x 16 q-rows). K-tiles of 64 keys,
// cp.async double-buffered. Writes (1-w)*softmax(QK^T)V into M (f32).
// SMEM: Q hi/lo [128][72] resident; per-buf K/V hi/lo [64][72]
// ---------------------------------------------------------------------------
constexpr int AL   = 72;                   // smem row stride (elems)
constexpr int AQT  = 128 * AL * 2;         // 18432 per Q tile
constexpr int AKT  = 64 * AL * 2;          // 9216 per K/V tile
constexpr int AKV  = 4 * AKT;              // 36864 per buffer
constexpr int ASM  = 2 * AQT + 2 * AKV;    // 110592

__global__ void __launch_bounds__(256)
attn_mma(const bf16* __restrict__ Qh, const bf16* __restrict__ Ql,
         const bf16* __restrict__ Kh, const bf16* __restrict__ Kl,
         const bf16* __restrict__ Vh, const bf16* __restrict__ Vl,
         float* __restrict__ Mout)
{
    extern __shared__ char sm[];
    const uint32_t su = smem_u32(sm);
    const int tid = threadIdx.x;
    const int w = tid >> 5, lane = tid & 31;
    const int b = blockIdx.z, h = blockIdx.y, qt = blockIdx.x;
    const size_t tokQ = (size_t)b * T_ + qt * 128;
    const int lrow = lane & 15, lcol8 = (lane >> 4) * 8;
    const int g = lane >> 2, tg = lane & 3;
    const int i4 = lane >> 3, r8 = lane & 7;      // for trans ldmatrix

    // Q tiles (hi, lo)
    {
        const bf16* qs[2] = { Qh, Ql };
#pragma unroll
        for (int t = 0; t < 2; t++)
#pragma unroll
            for (int r = 0; r < 4; r++) {
                int id = r * 256 + tid;
                int row = id >> 3, q = id & 7;
                CP16(su + t * AQT + row * (AL * 2) + q * 16,
                     qs[t] + (tokQ + row) * D_ + h * HC_ + q * 8);
            }
    }
    const bf16* kvs[4] = { Kh, Kl, Vh, Vl };
    auto load_kv = [&](int kt, int buf) {
        const size_t tok = (size_t)b * T_ + kt * 64;
#pragma unroll
        for (int t = 0; t < 4; t++)
#pragma unroll
            for (int r = 0; r < 2; r++) {
                int id = r * 256 + tid;
                int row = id >> 3, q = id & 7;
                CP16(su + 2 * AQT + buf * AKV + t * AKT + row * (AL * 2) + q * 16,
                     kvs[t] + (tok + row) * D_ + h * HC_ + q * 8);
            }
    };
    load_kv(0, 0); CP_COMMIT();

    float o[8][4] = {};
    float m0r = -1e30f, m1r = -1e30f, l0 = 0.f, l1 = 0.f;

    const int NKT = T_ / 64;   // 32
    for (int kt = 0; kt < NKT; kt++) {
        if (kt < NKT - 1) { load_kv(kt + 1, (kt + 1) & 1); CP_COMMIT(); CP_WAIT(1); }
        else              { CP_WAIT(0); }
        __syncthreads();
        const uint32_t kv = su + 2 * AQT + (kt & 1) * AKV;

        // ---- S = Q K^T (3-term split), 16 q x 64 k per warp ----
        float sc[8][4] = {};
#pragma unroll
        for (int kk = 0; kk < 4; kk++) {
            const int kc = kk * 16 + lcol8;
            uint32_t aq[4], aql[4];
            {
                uint32_t ar = su + ((w * 16 + lrow) * AL + kc) * 2;
                ldsm4(aq[0], aq[1], aq[2], aq[3], ar);
                ldsm4(aql[0], aql[1], aql[2], aql[3], ar + AQT);
            }
            uint32_t bh[8][2], bl[8][2];
#pragma unroll
            for (int np = 0; np < 4; np++) {
                uint32_t br = kv + ((np * 16 + lrow) * AL + kc) * 2;
                uint32_t r0, r1, r2, r3;
                ldsm4(r0, r1, r2, r3, br);
                bh[2*np][0] = r0; bh[2*np][1] = r2;
                bh[2*np+1][0] = r1; bh[2*np+1][1] = r3;
                ldsm4(r0, r1, r2, r3, br + AKT);
                bl[2*np][0] = r0; bl[2*np][1] = r2;
                bl[2*np+1][0] = r1; bl[2*np+1][1] = r3;
            }
#pragma unroll
            for (int nt = 0; nt < 8; nt++) {
                mma16816(sc[nt], aq, bh[nt]);
                mma16816(sc[nt], aq, bl[nt]);
                mma16816(sc[nt], aql, bh[nt]);
            }
        }

        // ---- online softmax (rows g and g+8, quad-wide) ----
        float mx0 = -1e30f, mx1 = -1e30f;
#pragma unroll
        for (int nt = 0; nt < 8; nt++) {
            mx0 = fmaxf(mx0, fmaxf(sc[nt][0], sc[nt][1]));
            mx1 = fmaxf(mx1, fmaxf(sc[nt][2], sc[nt][3]));
        }
        mx0 = fmaxf(mx0, __shfl_xor_sync(0xffffffffu, mx0, 1));
        mx0 = fmaxf(mx0, __shfl_xor_sync(0xffffffffu, mx0, 2));
        mx1 = fmaxf(mx1, __shfl_xor_sync(0xffffffffu, mx1, 1));
        mx1 = fmaxf(mx1, __shfl_xor_sync(0xffffffffu, mx1, 2));
        const float mn0 = fmaxf(m0r, mx0), mn1 = fmaxf(m1r, mx1);
        const float s0 = __expf(m0r - mn0), s1 = __expf(m1r - mn1);
        m0r = mn0; m1r = mn1;
        float sum0 = 0.f, sum1 = 0.f;
#pragma unroll
        for (int nt = 0; nt < 8; nt++) {
            sc[nt][0] = __expf(sc[nt][0] - mn0);
            sc[nt][1] = __expf(sc[nt][1] - mn0);
            sc[nt][2] = __expf(sc[nt][2] - mn1);
            sc[nt][3] = __expf(sc[nt][3] - mn1);
            sum0 += sc[nt][0] + sc[nt][1];
            sum1 += sc[nt][2] + sc[nt][3];
            o[nt][0] *= s0; o[nt][1] *= s0;
            o[nt][2] *= s1; o[nt][3] *= s1;
        }
        sum0 += __shfl_xor_sync(0xffffffffu, sum0, 1);
        sum0 += __shfl_xor_sync(0xffffffffu, sum0, 2);
        sum1 += __shfl_xor_sync(0xffffffffu, sum1, 1);
        sum1 += __shfl_xor_sync(0xffffffffu, sum1, 2);
        l0 = l0 * s0 + sum0;
        l1 = l1 * s1 + sum1;

        // ---- O += P V  (P split into hi/lo) ----
#pragma unroll
        for (int kk = 0; kk < 4; kk++) {
            // a-frags from probability fragments (tiles 2kk, 2kk+1)
            float p0 = sc[2*kk][0],   p1 = sc[2*kk][1];
            float p2 = sc[2*kk][2],   p3 = sc[2*kk][3];
            float p4 = sc[2*kk+1][0], p5 = sc[2*kk+1][1];
            float p6 = sc[2*kk+1][2], p7 = sc[2*kk+1][3];
            uint32_t ph[4], pl[4];
            ph[0] = packbf(p0, p1); ph[1] = packbf(p2, p3);
            ph[2] = packbf(p4, p5); ph[3] = packbf(p6, p7);
            float q0 = p0 - __bfloat162float(__float2bfloat16_rn(p0));
            float q1 = p1 - __bfloat162float(__float2bfloat16_rn(p1));
            float q2 = p2 - __bfloat162float(__float2bfloat16_rn(p2));
            float q3 = p3 - __bfloat162float(__float2bfloat16_rn(p3));
            float q4 = p4 - __bfloat162float(__float2bfloat16_rn(p4));
            float q5 = p5 - __bfloat162float(__float2bfloat16_rn(p5));
            float q6 = p6 - __bfloat162float(__float2bfloat16_rn(p6));
            float q7 = p7 - __bfloat162float(__float2bfloat16_rn(p7));
            pl[0] = packbf(q0, q1); pl[1] = packbf(q2, q3);
            pl[2] = packbf(q4, q5); pl[3] = packbf(q6, q7);

            uint32_t vh[8][2], vl[8][2];
#pragma unroll
            for (int np = 0; np < 4; np++) {
                // trans blocks: (k0,n0),(k0+8,n0),(k0,n0+8),(k0+8,n0+8)
                int krow = kk * 16 + (i4 & 1) * 8 + r8;
                int ncol = np * 16 + (i4 >> 1) * 8;
                uint32_t vr = kv + 2 * AKT + (krow * AL + ncol) * 2;
                uint32_t r0, r1, r2, r3;
                ldsm4t(r0, r1, r2, r3, vr);
                vh[2*np][0] = r0; vh[2*np][1] = r1;
                vh[2*np+1][0] = r2; vh[2*np+1][1] = r3;
                ldsm4t(r0, r1, r2, r3, vr + AKT);
                vl[2*np][0] = r0; vl[2*np][1] = r1;
                vl[2*np+1][0] = r2; vl[2*np+1][1] = r3;
            }
#pragma unroll
            for (int nt = 0; nt < 8; nt++) {
                mma16816(o[nt], ph, vh[nt]);
                mma16816(o[nt], pl, vh[nt]);
                mma16816(o[nt], ph, vl[nt]);
            }
        }
        __syncthreads();
    }

    // epilogue: O * (1-w) / l
    const float wgt = 1.f - g_w;
    const float i0 = wgt / l0, i1 = wgt / l1;
    const size_t row0 = tokQ + w * 16 + g;
    float* Mp0 = Mout + row0 * D_ + h * HC_;
    float* Mp1 = Mout + (row0 + 8) * D_ + h * HC_;
#pragma unroll
    for (int nt = 0; nt < 8; nt++) {
        float2 v0; v0.x = o[nt][0] * i0; v0.y = o[nt][1] * i0;
        float2 v1; v1.x = o[nt][2] * i1; v1.y = o[nt][3] * i1;
        *(float2*)(Mp0 + nt * 8 + tg * 2) = v0;
        *(float2*)(Mp1 + nt * 8 + tg * 2) = v1;
    }
}

// ---------------------------------------------------------------------------
// Setup / prefix / pwin (unchanged, known-correct)
// ---------------------------------------------------------------------------
__global__ void setup_kernel(const float* __restrict__ mu,
                             const float* __restrict__ lam,
                             const float* __restrict__ g1,
                             const float* __restrict__ g2,
                             const float* __restrict__ t1,
                             const float* __restrict__ t2)
{
    int tid = threadIdx.x;
    if (tid == 0) g_w = 1.f / (1.f + expf(-mu[0]));
    for (int idx = tid; idx < NH_ * 101; idx += blockDim.x) {
        int h = idx / 101, L = idx % 101;
        float Lf = (float)L;
        float val;
        if (h < 4) {
            float base = lam[h];
            float mag  = expf(Lf * logf(fabsf(base)));
            float sgn  = (base < 0.f) ? (1.f - 2.f * (float)(L & 1)) : 1.f;
            val = mag * sgn;
        } else if (h < 10) {
            int s = h - 4;
            val = expf(Lf * logf(g1[s])) * sinf(t1[s] * Lf);
        } else {
            int s = h - 10;
            val = expf(Lf * logf(g2[s])) * cosf(t2[s] * Lf);
        }
        g_f[h][L] = val;
    }
}

__global__ void prefix_kernel(const float* __restrict__ V, float* __restrict__ P)
{
    int idx = blockIdx.x * blockDim.x + threadIdx.x;
    int b = idx >> 10, d = idx & 1023;
    size_t base = (size_t)(b * T_) * D_ + d;
    float s = 0.f;
#pragma unroll 4
    for (int t = 0; t < T_; t++) {
        s += V[base + (size_t)t * D_];
        P[base + (size_t)t * D_] = s;
    }
}

__global__ void pwin_kernel(const float* __restrict__ V,
                            const float* __restrict__ PRE,
                            float* __restrict__ M)
{
    int c = threadIdx.x;
    int t = blockIdx.x * blockDim.y + threadIdx.y;
    int h = blockIdx.y, b = blockIdx.z;
    const float* f = g_f[h];
    size_t colbase = (size_t)(b * T_) * D_ + (size_t)h * HC_ + c;

    float acc = 0.f;
    int dmax = min(t, 99);
    for (int d = 1; d <= dmax; d++)
        acc += f[d] * V[colbase + (size_t)(t - d) * D_];
    if (t >= 100)
        acc += f[100] * PRE[colbase + (size_t)(t - 100) * D_];

    M[colbase + (size_t)t * D_] += g_w * acc;
}

// ---------------------------------------------------------------------------
// Launch
// ---------------------------------------------------------------------------
extern "C" void kernel_launch(void* const* d_in, const int* in_sizes, int n_in,
                              void* d_out, int out_size)
{
    const float* x   = (const float*)d_in[0];
    const float* mu  = (const float*)d_in[1];
    const float* lam = (const float*)d_in[2];
    const float* g1  = (const float*)d_in[3];
    const float* g2  = (const float*)d_in[4];
    const float* t1  = (const float*)d_in[5];
    const float* t2  = (const float*)d_in[6];
    const float* Wq  = (const float*)d_in[7];
    const float* bq  = (const float*)d_in[8];
    const float* Wk  = (const float*)d_in[9];
    const float* bk  = (const float*)d_in[10];
    const float* Wv  = (const float*)d_in[11];
    const float* bv  = (const float*)d_in[12];
    const float* Wf  = (const float*)d_in[13];
    const float* bf  = (const float*)d_in[14];
    float* out = (float*)d_out;

    float *Vb, *Mb, *PREb;
    cudaGetSymbolAddress((void**)&Vb,   g_V);
    cudaGetSymbolAddress((void**)&Mb,   g_M);
    cudaGetSymbolAddress((void**)&PREb, g_PRE);
    bf16 *xh, *xl, *Mh, *Ml, *Wh, *Wl, *Qh, *Ql, *Kh, *Kl, *Vh, *Vl;
    cudaGetSymbolAddress((void**)&xh, g_xh);
    cudaGetSymbolAddress((void**)&xl, g_xl);
    cudaGetSymbolAddress((void**)&Mh, g_Mh);
    cudaGetSymbolAddress((void**)&Ml, g_Ml);
    cudaGetSymbolAddress((void**)&Wh, g_Wh);
    cudaGetSymbolAddress((void**)&Wl, g_Wl);
    cudaGetSymbolAddress((void**)&Qh, g_Qh);
    cudaGetSymbolAddress((void**)&Ql, g_Ql);
    cudaGetSymbolAddress((void**)&Kh, g_Kh);
    cudaGetSymbolAddress((void**)&Kl, g_Kl);
    cudaGetSymbolAddress((void**)&Vh, g_Vh);
    cudaGetSymbolAddress((void**)&Vl, g_Vl);

    cudaFuncSetAttribute(tc_gemm,
                         cudaFuncAttributeMaxDynamicSharedMemorySize, GSMEM);
    cudaFuncSetAttribute(attn_mma,
                         cudaFuncAttributeMaxDynamicSharedMemorySize, ASM);

    setup_kernel<<<1, 128>>>(mu, lam, g1, g2, t1, t2);

    const size_t WN = (size_t)D_ * D_;
    const int n4x = NTOK_ * D_ / 4, n4w = (int)(WN / 4);
    split_kernel<<<(n4x + 255) / 256, 256>>>(x,  xh, xl, n4x);
    split_kernel<<<(n4w + 255) / 256, 256>>>(Wq, Wh + 0 * WN, Wl + 0 * WN, n4w);
    split_kernel<<<(n4w + 255) / 256, 256>>>(Wk, Wh + 1 * WN, Wl + 1 * WN, n4w);
    split_kernel<<<(n4w + 255) / 256, 256>>>(Wv, Wh + 2 * WN, Wl + 2 * WN, n4w);
    split_kernel<<<(n4w + 255) / 256, 256>>>(Wf, Wh + 3 * WN, Wl + 3 * WN, n4w);

    dim3 tg(NTOK_ / 128, D_ / 128);
    // Q, K: split outputs only.  V: f32 + split.
    tc_gemm<<<tg, 256, GSMEM>>>(xh, xl, Wh + 0 * WN, Wl + 0 * WN, bq, nullptr, Qh, Ql);
    tc_gemm<<<tg, 256, GSMEM>>>(xh, xl, Wh + 1 * WN, Wl + 1 * WN, bk, nullptr, Kh, Kl);
    tc_gemm<<<tg, 256, GSMEM>>>(xh, xl, Wh + 2 * WN, Wl + 2 * WN, bv, Vb, Vh, Vl);

    prefix_kernel<<<16, 256>>>(Vb, PREb);

    dim3 agrid(T_ / 128, NH_, B_);
    attn_mma<<<agrid, 256, ASM>>>(Qh, Ql, Kh, Kl, Vh, Vl, Mb);

    dim3 pblock(64, 4);
    dim3 pgrid(T_ / 4, NH_, B_);
    pwin_kernel<<<pgrid, pblock>>>(Vb, PREb, Mb);

    split_kernel<<<(n4x + 255) / 256, 256>>>(Mb, Mh, Ml, n4x);
    tc_gemm<<<tg, 256, GSMEM>>>(Mh, Ml, Wh + 3 * WN, Wl + 3 * WN, bf, out, nullptr, nullptr);
}

// round 4
// speedup vs baseline: 3.4321x; 1.4887x over previous
#include <cuda_runtime.h>
#include <cuda_fp16.h>
#include <math.h>
#include <cstdint>

using h16 = __half;

// ---------------------------------------------------------------------------
// Shapes
// ---------------------------------------------------------------------------
constexpr int B_    = 4;
constexpr int T_    = 2048;
constexpr int D_    = 1024;
constexpr int NH_   = 16;
constexpr int HC_   = 64;
constexpr int NTOK_ = B_ * T_;      // 8192

// ---------------------------------------------------------------------------
// Scratch (device globals)
// ---------------------------------------------------------------------------
__device__ float g_V  [(size_t)NTOK_ * D_];
__device__ float g_M  [(size_t)NTOK_ * D_];
__device__ float g_PRE[(size_t)NTOK_ * D_];
__device__ float g_part[4 * 16 * 1024];
__device__ float g_f[NH_][101];
__device__ float g_w;

__device__ h16 g_xh[(size_t)NTOK_ * D_];
__device__ h16 g_xl[(size_t)NTOK_ * D_];
__device__ h16 g_Mh[(size_t)NTOK_ * D_];
__device__ h16 g_Ml[(size_t)NTOK_ * D_];
__device__ h16 g_Wh[3][(size_t)D_ * D_];   // Wq, Wk, Wv hi
__device__ h16 g_Wl[3][(size_t)D_ * D_];   // Wq, Wk, Wv lo
__device__ h16 g_Wf1[(size_t)D_ * D_];     // Wf single fp16
__device__ h16 g_Qh[(size_t)NTOK_ * D_];
__device__ h16 g_Ql[(size_t)NTOK_ * D_];
__device__ h16 g_Kh[(size_t)NTOK_ * D_];
__device__ h16 g_Kl[(size_t)NTOK_ * D_];
__device__ h16 g_V1[(size_t)NTOK_ * D_];   // V single fp16

// ---------------------------------------------------------------------------
// PTX helpers (sm_80-era, valid on plain sm_103 target)
// ---------------------------------------------------------------------------
__device__ __forceinline__ uint32_t smem_u32(const void* p) {
    uint32_t a;
    asm("{ .reg .u64 t; cvta.to.shared.u64 t, %1; cvt.u32.u64 %0, t; }"
        : "=r"(a) : "l"(p));
    return a;
}
#define CP16(s, g) \
    asm volatile("cp.async.cg.shared.global [%0], [%1], 16;" \
                 :: "r"(s), "l"(g) : "memory")
#define CP_COMMIT() asm volatile("cp.async.commit_group;" ::: "memory")
#define CP_WAIT(n)  asm volatile("cp.async.wait_group %0;" :: "n"(n) : "memory")

__device__ __forceinline__ void ldsm4(uint32_t& r0, uint32_t& r1,
                                      uint32_t& r2, uint32_t& r3, uint32_t a) {
    asm volatile("ldmatrix.sync.aligned.m8n8.x4.shared.b16 {%0,%1,%2,%3}, [%4];"
                 : "=r"(r0), "=r"(r1), "=r"(r2), "=r"(r3) : "r"(a));
}
__device__ __forceinline__ void ldsm4t(uint32_t& r0, uint32_t& r1,
                                       uint32_t& r2, uint32_t& r3, uint32_t a) {
    asm volatile("ldmatrix.sync.aligned.m8n8.x4.trans.shared.b16 {%0,%1,%2,%3}, [%4];"
                 : "=r"(r0), "=r"(r1), "=r"(r2), "=r"(r3) : "r"(a));
}
__device__ __forceinline__ void mma16816(float* c, const uint32_t* a, const uint32_t* b) {
    asm volatile(
        "mma.sync.aligned.m16n8k16.row.col.f32.f16.f16.f32 "
        "{%0,%1,%2,%3},{%4,%5,%6,%7},{%8,%9},{%0,%1,%2,%3};"
        : "+f"(c[0]), "+f"(c[1]), "+f"(c[2]), "+f"(c[3])
        : "r"(a[0]), "r"(a[1]), "r"(a[2]), "r"(a[3]), "r"(b[0]), "r"(b[1]));
}
// pack {lo half <- first arg, hi half <- second arg} as fp16x2 (rn)
__device__ __forceinline__ uint32_t packh(float lo, float hi) {
    uint32_t r;
    asm("cvt.rn.f16x2.f32 %0, %1, %2;" : "=r"(r) : "f"(hi), "f"(lo));
    return r;
}

// ---------------------------------------------------------------------------
// fp32 -> fp16 (hi, lo) split, and fp32 -> fp16 single
// ---------------------------------------------------------------------------
__global__ void split_kernel(const float* __restrict__ s,
                             h16* __restrict__ hi, h16* __restrict__ lo, int n4)
{
    int i = blockIdx.x * blockDim.x + threadIdx.x;
    if (i >= n4) return;
    float4 a = ((const float4*)s)[i];
    float h0 = __half2float(__float2half_rn(a.x));
    float h1 = __half2float(__float2half_rn(a.y));
    float h2 = __half2float(__float2half_rn(a.z));
    float h3 = __half2float(__float2half_rn(a.w));
    uint2 H, L;
    H.x = packh(a.x, a.y);            H.y = packh(a.z, a.w);
    L.x = packh(a.x - h0, a.y - h1);  L.y = packh(a.z - h2, a.w - h3);
    ((uint2*)hi)[i] = H;
    ((uint2*)lo)[i] = L;
}

__global__ void cvt1_kernel(const float* __restrict__ s, h16* __restrict__ o, int n4)
{
    int i = blockIdx.x * blockDim.x + threadIdx.x;
    if (i >= n4) return;
    float4 a = ((const float4*)s)[i];
    uint2 H;
    H.x = packh(a.x, a.y);  H.y = packh(a.z, a.w);
    ((uint2*)o)[i] = H;
}

// ---------------------------------------------------------------------------
// Fused QKV NT GEMM (3-term fp16 split, exact to ~2^-22)
// grid (64, 8, 3): z picks {Q, K, V}. CTA 128x128, BK=32, 8 warps
// ---------------------------------------------------------------------------
constexpr int GL   = 40;                   // smem row stride (halves)
constexpr int GTB  = 128 * GL * 2;         // 10240 B per tile
constexpr int GBUF3 = 4 * GTB;             // Ah,Al,Bh,Bl
constexpr int GSMEM3 = 2 * GBUF3;          // 81920

__global__ void __launch_bounds__(256)
qkv_gemm(const h16* __restrict__ xh, const h16* __restrict__ xl,
         const h16* __restrict__ W0h, const h16* __restrict__ W0l,
         const h16* __restrict__ W1h, const h16* __restrict__ W1l,
         const h16* __restrict__ W2h, const h16* __restrict__ W2l,
         const float* __restrict__ b0, const float* __restrict__ b1,
         const float* __restrict__ b2,
         h16* __restrict__ Qh, h16* __restrict__ Ql,
         h16* __restrict__ Kh, h16* __restrict__ Kl,
         float* __restrict__ Vf, h16* __restrict__ V1)
{
    extern __shared__ char sm[];
    const uint32_t su = smem_u32(sm);
    const int tid = threadIdx.x;
    const int wid = tid >> 5, lane = tid & 31;
    const int wm = wid & 1, wn = wid >> 1;
    const int m0 = blockIdx.x * 128, n0 = blockIdx.y * 128;
    const int z = blockIdx.z;

    const h16* Bh = (z == 0) ? W0h : (z == 1) ? W1h : W2h;
    const h16* Bl = (z == 0) ? W0l : (z == 1) ? W1l : W2l;
    const float* bias = (z == 0) ? b0 : (z == 1) ? b1 : b2;

    const h16* srcs[4] = { xh + (size_t)m0 * D_, xl + (size_t)m0 * D_,
                           Bh + (size_t)n0 * D_, Bl + (size_t)n0 * D_ };

    const int lrow = lane & 15, lcol8 = (lane >> 4) * 8;
    const int g = lane >> 2, tg = lane & 3;

    auto load_chunk = [&](int c, int buf) {
        const int k0 = c * 32;
#pragma unroll
        for (int t = 0; t < 4; t++)
#pragma unroll
            for (int r = 0; r < 2; r++) {
                int id = r * 256 + tid;
                int row = id >> 2, q = id & 3;
                CP16(su + buf * GBUF3 + t * GTB + row * 80 + q * 16,
                     srcs[t] + (size_t)row * D_ + k0 + q * 8);
            }
    };

    load_chunk(0, 0); CP_COMMIT();

    float acc[4][4][4] = {};

    for (int c = 0; c < 32; c++) {
        if (c < 31) { load_chunk(c + 1, (c + 1) & 1); CP_COMMIT(); CP_WAIT(1); }
        else        { CP_WAIT(0); }
        __syncthreads();
        const uint32_t base = su + (c & 1) * GBUF3;
#pragma unroll
        for (int k2 = 0; k2 < 2; k2++) {
            const int kc = k2 * 16 + lcol8;
            uint32_t ah[4][4], al[4][4];
#pragma unroll
            for (int mt = 0; mt < 4; mt++) {
                uint32_t ar = base + ((wm * 64 + mt * 16 + lrow) * GL + kc) * 2;
                ldsm4(ah[mt][0], ah[mt][1], ah[mt][2], ah[mt][3], ar);
                ldsm4(al[mt][0], al[mt][1], al[mt][2], al[mt][3], ar + GTB);
            }
            uint32_t bh[4][2], bl[4][2];
#pragma unroll
            for (int np = 0; np < 2; np++) {
                uint32_t br = base + 2 * GTB + ((wn * 32 + np * 16 + lrow) * GL + kc) * 2;
                uint32_t r0, r1, r2, r3;
                ldsm4(r0, r1, r2, r3, br);
                bh[2*np][0] = r0; bh[2*np][1] = r2;
                bh[2*np+1][0] = r1; bh[2*np+1][1] = r3;
                ldsm4(r0, r1, r2, r3, br + GTB);
                bl[2*np][0] = r0; bl[2*np][1] = r2;
                bl[2*np+1][0] = r1; bl[2*np+1][1] = r3;
            }
#pragma unroll
            for (int mt = 0; mt < 4; mt++)
#pragma unroll
                for (int nt = 0; nt < 4; nt++) {
                    mma16816(acc[mt][nt], ah[mt], bh[nt]);
                    mma16816(acc[mt][nt], ah[mt], bl[nt]);
                    mma16816(acc[mt][nt], al[mt], bh[nt]);
                }
        }
        __syncthreads();
    }

    h16* Ch = (z == 0) ? Qh : Kh;
    h16* Cl = (z == 0) ? Ql : Kl;
#pragma unroll
    for (int mt = 0; mt < 4; mt++)
#pragma unroll
        for (int nt = 0; nt < 4; nt++) {
            const int col = n0 + wn * 32 + nt * 8 + tg * 2;
            const float b0v = bias[col], b1v = bias[col + 1];
#pragma unroll
            for (int hf = 0; hf < 2; hf++) {
                const int row = m0 + wm * 64 + mt * 16 + g + hf * 8;
                float v0 = acc[mt][nt][hf * 2]     + b0v;
                float v1 = acc[mt][nt][hf * 2 + 1] + b1v;
                if (z == 2) {
                    float2 o; o.x = v0; o.y = v1;
                    *(float2*)(Vf + (size_t)row * D_ + col) = o;
                    *(uint32_t*)(V1 + (size_t)row * D_ + col) = packh(v0, v1);
                } else {
                    float h0 = __half2float(__float2half_rn(v0));
                    float h1 = __half2float(__float2half_rn(v1));
                    *(uint32_t*)(Ch + (size_t)row * D_ + col) = packh(v0, v1);
                    *(uint32_t*)(Cl + (size_t)row * D_ + col) = packh(v0 - h0, v1 - h1);
                }
            }
        }
}

// ---------------------------------------------------------------------------
// Output projection NT GEMM (2-term: M hi/lo x Wf single)
// ---------------------------------------------------------------------------
constexpr int GBUF2 = 3 * GTB;
constexpr int GSMEM2 = 2 * GBUF2;          // 61440

__global__ void __launch_bounds__(256)
out_gemm(const h16* __restrict__ Ah, const h16* __restrict__ Al,
         const h16* __restrict__ Bs, const float* __restrict__ bias,
         float* __restrict__ Cf)
{
    extern __shared__ char sm[];
    const uint32_t su = smem_u32(sm);
    const int tid = threadIdx.x;
    const int wid = tid >> 5, lane = tid & 31;
    const int wm = wid & 1, wn = wid >> 1;
    const int m0 = blockIdx.x * 128, n0 = blockIdx.y * 128;

    const h16* srcs[3] = { Ah + (size_t)m0 * D_, Al + (size_t)m0 * D_,
                           Bs + (size_t)n0 * D_ };

    const int lrow = lane & 15, lcol8 = (lane >> 4) * 8;
    const int g = lane >> 2, tg = lane & 3;

    auto load_chunk = [&](int c, int buf) {
        const int k0 = c * 32;
#pragma unroll
        for (int t = 0; t < 3; t++)
#pragma unroll
            for (int r = 0; r < 2; r++) {
                int id = r * 256 + tid;
                int row = id >> 2, q = id & 3;
                CP16(su + buf * GBUF2 + t * GTB + row * 80 + q * 16,
                     srcs[t] + (size_t)row * D_ + k0 + q * 8);
            }
    };

    load_chunk(0, 0); CP_COMMIT();

    float acc[4][4][4] = {};

    for (int c = 0; c < 32; c++) {
        if (c < 31) { load_chunk(c + 1, (c + 1) & 1); CP_COMMIT(); CP_WAIT(1); }
        else        { CP_WAIT(0); }
        __syncthreads();
        const uint32_t base = su + (c & 1) * GBUF2;
#pragma unroll
        for (int k2 = 0; k2 < 2; k2++) {
            const int kc = k2 * 16 + lcol8;
            uint32_t ah[4][4], al[4][4];
#pragma unroll
            for (int mt = 0; mt < 4; mt++) {
                uint32_t ar = base + ((wm * 64 + mt * 16 + lrow) * GL + kc) * 2;
                ldsm4(ah[mt][0], ah[mt][1], ah[mt][2], ah[mt][3], ar);
                ldsm4(al[mt][0], al[mt][1], al[mt][2], al[mt][3], ar + GTB);
            }
            uint32_t bh[4][2];
#pragma unroll
            for (int np = 0; np < 2; np++) {
                uint32_t br = base + 2 * GTB + ((wn * 32 + np * 16 + lrow) * GL + kc) * 2;
                uint32_t r0, r1, r2, r3;
                ldsm4(r0, r1, r2, r3, br);
                bh[2*np][0] = r0; bh[2*np][1] = r2;
                bh[2*np+1][0] = r1; bh[2*np+1][1] = r3;
            }
#pragma unroll
            for (int mt = 0; mt < 4; mt++)
#pragma unroll
                for (int nt = 0; nt < 4; nt++) {
                    mma16816(acc[mt][nt], ah[mt], bh[nt]);
                    mma16816(acc[mt][nt], al[mt], bh[nt]);
                }
        }
        __syncthreads();
    }

#pragma unroll
    for (int mt = 0; mt < 4; mt++)
#pragma unroll
        for (int nt = 0; nt < 4; nt++) {
            const int col = n0 + wn * 32 + nt * 8 + tg * 2;
            const float b0v = bias[col], b1v = bias[col + 1];
#pragma unroll
            for (int hf = 0; hf < 2; hf++) {
                const int row = m0 + wm * 64 + mt * 16 + g + hf * 8;
                float2 o;
                o.x = acc[mt][nt][hf * 2]     + b0v;
                o.y = acc[mt][nt][hf * 2 + 1] + b1v;
                *(float2*)(Cf + (size_t)row * D_ + col) = o;
            }
        }
}

// ---------------------------------------------------------------------------
// HMMA flash attention: QK^T 3-term fp16 (exact-ish), PV single fp16 (1 MMA)
// CTA: 128 q-rows, 256 thr. K-tiles of 64 keys double-buffered.
// SMEM: Q hi/lo resident; per-buf Kh, Kl, V1 tiles.
// ---------------------------------------------------------------------------
constexpr int AL   = 72;
constexpr int AQT  = 128 * AL * 2;         // 18432
constexpr int AKT  = 64 * AL * 2;          // 9216
constexpr int AKV  = 3 * AKT;              // 27648
constexpr int ASM  = 2 * AQT + 2 * AKV;    // 92160

__global__ void __launch_bounds__(256)
attn_mma(const h16* __restrict__ Qh, const h16* __restrict__ Ql,
         const h16* __restrict__ Kh, const h16* __restrict__ Kl,
         const h16* __restrict__ V1, float* __restrict__ Mout)
{
    extern __shared__ char sm[];
    const uint32_t su = smem_u32(sm);
    const int tid = threadIdx.x;
    const int w = tid >> 5, lane = tid & 31;
    const int b = blockIdx.z, h = blockIdx.y, qt = blockIdx.x;
    const size_t tokQ = (size_t)b * T_ + qt * 128;
    const int lrow = lane & 15, lcol8 = (lane >> 4) * 8;
    const int g = lane >> 2, tg = lane & 3;
    const int i4 = lane >> 3, r8 = lane & 7;

    {
        const h16* qs[2] = { Qh, Ql };
#pragma unroll
        for (int t = 0; t < 2; t++)
#pragma unroll
            for (int r = 0; r < 4; r++) {
                int id = r * 256 + tid;
                int row = id >> 3, q = id & 7;
                CP16(su + t * AQT + row * (AL * 2) + q * 16,
                     qs[t] + (tokQ + row) * D_ + h * HC_ + q * 8);
            }
    }
    const h16* kvs[3] = { Kh, Kl, V1 };
    auto load_kv = [&](int kt, int buf) {
        const size_t tok = (size_t)b * T_ + kt * 64;
#pragma unroll
        for (int t = 0; t < 3; t++)
#pragma unroll
            for (int r = 0; r < 2; r++) {
                int id = r * 256 + tid;
                int row = id >> 3, q = id & 7;
                CP16(su + 2 * AQT + buf * AKV + t * AKT + row * (AL * 2) + q * 16,
                     kvs[t] + (tok + row) * D_ + h * HC_ + q * 8);
            }
    };
    load_kv(0, 0); CP_COMMIT();

    float o[8][4] = {};
    float m0r = -1e30f, m1r = -1e30f, l0 = 0.f, l1 = 0.f;

    const int NKT = T_ / 64;   // 32
    for (int kt = 0; kt < NKT; kt++) {
        if (kt < NKT - 1) { load_kv(kt + 1, (kt + 1) & 1); CP_COMMIT(); CP_WAIT(1); }
        else              { CP_WAIT(0); }
        __syncthreads();
        const uint32_t kv = su + 2 * AQT + (kt & 1) * AKV;

        // ---- S = Q K^T (3-term fp16 split) ----
        float sc[8][4] = {};
#pragma unroll
        for (int kk = 0; kk < 4; kk++) {
            const int kc = kk * 16 + lcol8;
            uint32_t aq[4], aql[4];
            {
                uint32_t ar = su + ((w * 16 + lrow) * AL + kc) * 2;
                ldsm4(aq[0], aq[1], aq[2], aq[3], ar);
                ldsm4(aql[0], aql[1], aql[2], aql[3], ar + AQT);
            }
            uint32_t bh[8][2], bl[8][2];
#pragma unroll
            for (int np = 0; np < 4; np++) {
                uint32_t br = kv + ((np * 16 + lrow) * AL + kc) * 2;
                uint32_t r0, r1, r2, r3;
                ldsm4(r0, r1, r2, r3, br);
                bh[2*np][0] = r0; bh[2*np][1] = r2;
                bh[2*np+1][0] = r1; bh[2*np+1][1] = r3;
                ldsm4(r0, r1, r2, r3, br + AKT);
                bl[2*np][0] = r0; bl[2*np][1] = r2;
                bl[2*np+1][0] = r1; bl[2*np+1][1] = r3;
            }
#pragma unroll
            for (int nt = 0; nt < 8; nt++) {
                mma16816(sc[nt], aq, bh[nt]);
                mma16816(sc[nt], aq, bl[nt]);
                mma16816(sc[nt], aql, bh[nt]);
            }
        }

        // ---- online softmax ----
        float mx0 = -1e30f, mx1 = -1e30f;
#pragma unroll
        for (int nt = 0; nt < 8; nt++) {
            mx0 = fmaxf(mx0, fmaxf(sc[nt][0], sc[nt][1]));
            mx1 = fmaxf(mx1, fmaxf(sc[nt][2], sc[nt][3]));
        }
        mx0 = fmaxf(mx0, __shfl_xor_sync(0xffffffffu, mx0, 1));
        mx0 = fmaxf(mx0, __shfl_xor_sync(0xffffffffu, mx0, 2));
        mx1 = fmaxf(mx1, __shfl_xor_sync(0xffffffffu, mx1, 1));
        mx1 = fmaxf(mx1, __shfl_xor_sync(0xffffffffu, mx1, 2));
        const float mn0 = fmaxf(m0r, mx0), mn1 = fmaxf(m1r, mx1);
        const float s0 = __expf(m0r - mn0), s1 = __expf(m1r - mn1);
        m0r = mn0; m1r = mn1;
        float sum0 = 0.f, sum1 = 0.f;
#pragma unroll
        for (int nt = 0; nt < 8; nt++) {
            sc[nt][0] = __expf(sc[nt][0] - mn0);
            sc[nt][1] = __expf(sc[nt][1] - mn0);
            sc[nt][2] = __expf(sc[nt][2] - mn1);
            sc[nt][3] = __expf(sc[nt][3] - mn1);
            sum0 += sc[nt][0] + sc[nt][1];
            sum1 += sc[nt][2] + sc[nt][3];
            o[nt][0] *= s0; o[nt][1] *= s0;
            o[nt][2] *= s1; o[nt][3] *= s1;
        }
        sum0 += __shfl_xor_sync(0xffffffffu, sum0, 1);
        sum0 += __shfl_xor_sync(0xffffffffu, sum0, 2);
        sum1 += __shfl_xor_sync(0xffffffffu, sum1, 1);
        sum1 += __shfl_xor_sync(0xffffffffu, sum1, 2);
        l0 = l0 * s0 + sum0;
        l1 = l1 * s1 + sum1;

        // ---- O += P V  (single fp16 P, single fp16 V: 1 MMA per tile) ----
#pragma unroll
        for (int kk = 0; kk < 4; kk++) {
            uint32_t ph[4];
            ph[0] = packh(sc[2*kk][0],   sc[2*kk][1]);
            ph[1] = packh(sc[2*kk][2],   sc[2*kk][3]);
            ph[2] = packh(sc[2*kk+1][0], sc[2*kk+1][1]);
            ph[3] = packh(sc[2*kk+1][2], sc[2*kk+1][3]);

            uint32_t vh[8][2];
#pragma unroll
            for (int np = 0; np < 4; np++) {
                int krow = kk * 16 + (i4 & 1) * 8 + r8;
                int ncol = np * 16 + (i4 >> 1) * 8;
                uint32_t vr = kv + 2 * AKT + (krow * AL + ncol) * 2;
                uint32_t r0, r1, r2, r3;
                ldsm4t(r0, r1, r2, r3, vr);
                vh[2*np][0] = r0; vh[2*np][1] = r1;
                vh[2*np+1][0] = r2; vh[2*np+1][1] = r3;
            }
#pragma unroll
            for (int nt = 0; nt < 8; nt++)
                mma16816(o[nt], ph, vh[nt]);
        }
        __syncthreads();
    }

    const float wgt = 1.f - g_w;
    const float i0 = wgt / l0, i1 = wgt / l1;
    const size_t row0 = tokQ + w * 16 + g;
    float* Mp0 = Mout + row0 * D_ + h * HC_;
    float* Mp1 = Mout + (row0 + 8) * D_ + h * HC_;
#pragma unroll
    for (int nt = 0; nt < 8; nt++) {
        float2 v0; v0.x = o[nt][0] * i0; v0.y = o[nt][1] * i0;
        float2 v1; v1.x = o[nt][2] * i1; v1.y = o[nt][3] * i1;
        *(float2*)(Mp0 + nt * 8 + tg * 2) = v0;
        *(float2*)(Mp1 + nt * 8 + tg * 2) = v1;
    }
}

// ---------------------------------------------------------------------------
// Setup
// ---------------------------------------------------------------------------
__global__ void setup_kernel(const float* __restrict__ mu,
                             const float* __restrict__ lam,
                             const float* __restrict__ g1,
                             const float* __restrict__ g2,
                             const float* __restrict__ t1,
                             const float* __restrict__ t2)
{
    int tid = threadIdx.x;
    if (tid == 0) g_w = 1.f / (1.f + expf(-mu[0]));
    for (int idx = tid; idx < NH_ * 101; idx += blockDim.x) {
        int h = idx / 101, L = idx % 101;
        float Lf = (float)L;
        float val;
        if (h < 4) {
            float base = lam[h];
            float mag  = expf(Lf * logf(fabsf(base)));
            float sgn  = (base < 0.f) ? (1.f - 2.f * (float)(L & 1)) : 1.f;
            val = mag * sgn;
        } else if (h < 10) {
            int s = h - 4;
            val = expf(Lf * logf(g1[s])) * sinf(t1[s] * Lf);
        } else {
            int s = h - 10;
            val = expf(Lf * logf(g2[s])) * cosf(t2[s] * Lf);
        }
        g_f[h][L] = val;
    }
}

// ---------------------------------------------------------------------------
// Parallel prefix sums of V along t (segmented two-pass)
// ---------------------------------------------------------------------------
__global__ void prefA(const float* __restrict__ V, float* __restrict__ part)
{
    int idx = blockIdx.x * blockDim.x + threadIdx.x;   // 65536
    int d = idx & 1023, seg = (idx >> 10) & 15, b = idx >> 14;
    size_t base = ((size_t)(b * T_) + seg * 128) * D_ + d;
    float s = 0.f;
#pragma unroll 4
    for (int i = 0; i < 128; i++) s += V[base + (size_t)i * D_];
    part[(b * 16 + seg) * 1024 + d] = s;
}

__global__ void prefC(const float* __restrict__ V, const float* __restrict__ part,
                      float* __restrict__ PRE)
{
    int idx = blockIdx.x * blockDim.x + threadIdx.x;
    int d = idx & 1023, seg = (idx >> 10) & 15, b = idx >> 14;
    float off = 0.f;
    for (int s2 = 0; s2 < seg; s2++) off += part[(b * 16 + s2) * 1024 + d];
    size_t base = ((size_t)(b * T_) + seg * 128) * D_ + d;
    float s = off;
#pragma unroll 4
    for (int i = 0; i < 128; i++) {
        s += V[base + (size_t)i * D_];
        PRE[base + (size_t)i * D_] = s;
    }
}

// ---------------------------------------------------------------------------
// P@V window conv via SMEM tiling: M += w * (P@V)
// block: (b, h, 128-token tile), 256 threads. Vs channel-major, stride 237.
// ---------------------------------------------------------------------------
constexpr int PWS   = 237;                          // odd stride, conflict-free
constexpr int PWSMEM = (104 + 64 * PWS) * 4;        // 61088 B

__global__ void __launch_bounds__(256)
pwin2(const float* __restrict__ V, const float* __restrict__ PRE,
      float* __restrict__ M)
{
    extern __shared__ float ps[];
    float* fs = ps;               // [104]
    float* Vs = ps + 104;         // [64][237], Vs[c*237 + r], r = local t + 100

    const int tid = threadIdx.x;
    const int t0 = blockIdx.x * 128, h = blockIdx.y, b = blockIdx.z;

    if (tid < 101) fs[tid] = g_f[h][tid];
    // load 228 rows x 64 ch (rows t0-100 .. t0+127), zero-fill t<0
    for (int id = tid; id < 228 * 16; id += 256) {
        int r = id >> 4, q = id & 15;
        int t = t0 - 100 + r;
        float4 v = make_float4(0.f, 0.f, 0.f, 0.f);
        if (t >= 0)
            v = *(const float4*)(V + ((size_t)(b * T_) + t) * D_ + h * HC_ + q * 4);
        Vs[(q * 4 + 0) * PWS + r] = v.x;
        Vs[(q * 4 + 1) * PWS + r] = v.y;
        Vs[(q * 4 + 2) * PWS + r] = v.z;
        Vs[(q * 4 + 3) * PWS + r] = v.w;
    }
    __syncthreads();

    const int c = tid & 63, tq = tid >> 6;
    const float f100 = fs[100];
    const float wv = g_w;
    const float* vc = Vs + c * PWS;

#pragma unroll 1
    for (int s = 0; s < 8; s++) {
        const int tb = (tq + 4 * s) * 4;       // local t offset of 4-group
        float a0 = 0.f, a1 = 0.f, a2 = 0.f, a3 = 0.f;
        // contributions: out[tb+i] += f[tb+i-j] * V[j],  1 <= d <= 99
#pragma unroll 4
        for (int j = tb - 99; j <= tb + 2; j++) {
            float v = vc[j + 100];
            int d0 = tb - j;
            if (d0 >= 1 && d0 <= 99)     a0 += fs[d0] * v;
            if (d0 + 1 >= 1 && d0 + 1 <= 99) a1 += fs[d0 + 1] * v;
            if (d0 + 2 >= 1 && d0 + 2 <= 99) a2 += fs[d0 + 2] * v;
            if (d0 + 3 >= 1 && d0 + 3 <= 99) a3 += fs[d0 + 3] * v;
        }
        float acc[4] = { a0, a1, a2, a3 };
#pragma unroll
        for (int i = 0; i < 4; i++) {
            int t = t0 + tb + i;
            float a = acc[i];
            if (t >= 100)
                a += f100 * PRE[((size_t)(b * T_) + t - 100) * D_ + h * HC_ + c];
            size_t o = ((size_t)(b * T_) + t) * D_ + h * HC_ + c;
            M[o] += wv * a;
        }
    }
}

// ---------------------------------------------------------------------------
// Launch
// ---------------------------------------------------------------------------
extern "C" void kernel_launch(void* const* d_in, const int* in_sizes, int n_in,
                              void* d_out, int out_size)
{
    const float* x   = (const float*)d_in[0];
    const float* mu  = (const float*)d_in[1];
    const float* lam = (const float*)d_in[2];
    const float* g1  = (const float*)d_in[3];
    const float* g2  = (const float*)d_in[4];
    const float* t1  = (const float*)d_in[5];
    const float* t2  = (const float*)d_in[6];
    const float* Wq  = (const float*)d_in[7];
    const float* bq  = (const float*)d_in[8];
    const float* Wk  = (const float*)d_in[9];
    const float* bk  = (const float*)d_in[10];
    const float* Wv  = (const float*)d_in[11];
    const float* bv  = (const float*)d_in[12];
    const float* Wf  = (const float*)d_in[13];
    const float* bf  = (const float*)d_in[14];
    float* out = (float*)d_out;

    float *Vb, *Mb, *PREb, *partb;
    cudaGetSymbolAddress((void**)&Vb,    g_V);
    cudaGetSymbolAddress((void**)&Mb,    g_M);
    cudaGetSymbolAddress((void**)&PREb,  g_PRE);
    cudaGetSymbolAddress((void**)&partb, g_part);
    h16 *xh, *xl, *Mh, *Ml, *Wh, *Wl, *Wf1, *Qh, *Ql, *Kh, *Kl, *V1;
    cudaGetSymbolAddress((void**)&xh,  g_xh);
    cudaGetSymbolAddress((void**)&xl,  g_xl);
    cudaGetSymbolAddress((void**)&Mh,  g_Mh);
    cudaGetSymbolAddress((void**)&Ml,  g_Ml);
    cudaGetSymbolAddress((void**)&Wh,  g_Wh);
    cudaGetSymbolAddress((void**)&Wl,  g_Wl);
    cudaGetSymbolAddress((void**)&Wf1, g_Wf1);
    cudaGetSymbolAddress((void**)&Qh,  g_Qh);
    cudaGetSymbolAddress((void**)&Ql,  g_Ql);
    cudaGetSymbolAddress((void**)&Kh,  g_Kh);
    cudaGetSymbolAddress((void**)&Kl,  g_Kl);
    cudaGetSymbolAddress((void**)&V1,  g_V1);

    cudaFuncSetAttribute(qkv_gemm,
                         cudaFuncAttributeMaxDynamicSharedMemorySize, GSMEM3);
    cudaFuncSetAttribute(out_gemm,
                         cudaFuncAttributeMaxDynamicSharedMemorySize, GSMEM2);
    cudaFuncSetAttribute(attn_mma,
                         cudaFuncAttributeMaxDynamicSharedMemorySize, ASM);
    cudaFuncSetAttribute(pwin2,
                         cudaFuncAttributeMaxDynamicSharedMemorySize, PWSMEM);

    setup_kernel<<<1, 128>>>(mu, lam, g1, g2, t1, t2);

    const size_t WN = (size_t)D_ * D_;
    const int n4x = NTOK_ * D_ / 4, n4w = (int)(WN / 4);
    split_kernel<<<(n4x + 255) / 256, 256>>>(x,  xh, xl, n4x);
    split_kernel<<<(n4w + 255) / 256, 256>>>(Wq, Wh + 0 * WN, Wl + 0 * WN, n4w);
    split_kernel<<<(n4w + 255) / 256, 256>>>(Wk, Wh + 1 * WN, Wl + 1 * WN, n4w);
    split_kernel<<<(n4w + 255) / 256, 256>>>(Wv, Wh + 2 * WN, Wl + 2 * WN, n4w);
    cvt1_kernel<<<(n4w + 255) / 256, 256>>>(Wf, Wf1, n4w);

    dim3 tg(NTOK_ / 128, D_ / 128, 3);
    qkv_gemm<<<tg, 256, GSMEM3>>>(xh, xl,
                                  Wh + 0 * WN, Wl + 0 * WN,
                                  Wh + 1 * WN, Wl + 1 * WN,
                                  Wh + 2 * WN, Wl + 2 * WN,
                                  bq, bk, bv,
                                  Qh, Ql, Kh, Kl, Vb, V1);

    prefA<<<256, 256>>>(Vb, partb);
    prefC<<<256, 256>>>(Vb, partb, PREb);

    dim3 agrid(T_ / 128, NH_, B_);
    attn_mma<<<agrid, 256, ASM>>>(Qh, Ql, Kh, Kl, V1, Mb);

    dim3 pgrid(T_ / 128, NH_, B_);
    pwin2<<<pgrid, 256, PWSMEM>>>(Vb, PREb, Mb);

    split_kernel<<<(n4x + 255) / 256, 256>>>(Mb, Mh, Ml, n4x);
    dim3 og(NTOK_ / 128, D_ / 128);
    out_gemm<<<og, 256, GSMEM2>>>(Mh, Ml, Wf1, bf, out);
}

// round 5
// speedup vs baseline: 3.5347x; 1.0299x over previous
#include <cuda_runtime.h>
#include <cuda_fp16.h>
#include <math.h>
#include <cstdint>

using h16 = __half;

// ---------------------------------------------------------------------------
// Shapes
// ---------------------------------------------------------------------------
constexpr int B_    = 4;
constexpr int T_    = 2048;
constexpr int D_    = 1024;
constexpr int NH_   = 16;
constexpr int HC_   = 64;
constexpr int NTOK_ = B_ * T_;      // 8192

// ---------------------------------------------------------------------------
// Scratch (device globals)
// ---------------------------------------------------------------------------
__device__ float g_V  [(size_t)NTOK_ * D_];
__device__ float g_M  [(size_t)NTOK_ * D_];
__device__ float g_PRE[(size_t)NTOK_ * D_];
__device__ float g_part[4 * 16 * 1024];
__device__ float g_f[NH_][101];
__device__ float g_w;

__device__ h16 g_xh[(size_t)NTOK_ * D_];
__device__ h16 g_xl[(size_t)NTOK_ * D_];
__device__ h16 g_Mh[(size_t)NTOK_ * D_];
__device__ h16 g_Ml[(size_t)NTOK_ * D_];
__device__ h16 g_Wh[3][(size_t)D_ * D_];   // Wq, Wk, Wv hi
__device__ h16 g_Wl[3][(size_t)D_ * D_];   // Wq, Wk, Wv lo
__device__ h16 g_Wf1[(size_t)D_ * D_];     // Wf single fp16
__device__ h16 g_Qh[(size_t)NTOK_ * D_];
__device__ h16 g_Ql[(size_t)NTOK_ * D_];
__device__ h16 g_Kh[(size_t)NTOK_ * D_];
__device__ h16 g_Kl[(size_t)NTOK_ * D_];
__device__ h16 g_V1[(size_t)NTOK_ * D_];   // V single fp16

// ---------------------------------------------------------------------------
// PTX helpers (sm_80-era, valid on plain sm_103 target)
// ---------------------------------------------------------------------------
__device__ __forceinline__ uint32_t smem_u32(const void* p) {
    uint32_t a;
    asm("{ .reg .u64 t; cvta.to.shared.u64 t, %1; cvt.u32.u64 %0, t; }"
        : "=r"(a) : "l"(p));
    return a;
}
#define CP16(s, g) \
    asm volatile("cp.async.cg.shared.global [%0], [%1], 16;" \
                 :: "r"(s), "l"(g) : "memory")
#define CP_COMMIT() asm volatile("cp.async.commit_group;" ::: "memory")
#define CP_WAIT(n)  asm volatile("cp.async.wait_group %0;" :: "n"(n) : "memory")

__device__ __forceinline__ void ldsm4(uint32_t& r0, uint32_t& r1,
                                      uint32_t& r2, uint32_t& r3, uint32_t a) {
    asm volatile("ldmatrix.sync.aligned.m8n8.x4.shared.b16 {%0,%1,%2,%3}, [%4];"
                 : "=r"(r0), "=r"(r1), "=r"(r2), "=r"(r3) : "r"(a));
}
__device__ __forceinline__ void ldsm4t(uint32_t& r0, uint32_t& r1,
                                       uint32_t& r2, uint32_t& r3, uint32_t a) {
    asm volatile("ldmatrix.sync.aligned.m8n8.x4.trans.shared.b16 {%0,%1,%2,%3}, [%4];"
                 : "=r"(r0), "=r"(r1), "=r"(r2), "=r"(r3) : "r"(a));
}
__device__ __forceinline__ void mma16816(float* c, const uint32_t* a, const uint32_t* b) {
    asm volatile(
        "mma.sync.aligned.m16n8k16.row.col.f32.f16.f16.f32 "
        "{%0,%1,%2,%3},{%4,%5,%6,%7},{%8,%9},{%0,%1,%2,%3};"
        : "+f"(c[0]), "+f"(c[1]), "+f"(c[2]), "+f"(c[3])
        : "r"(a[0]), "r"(a[1]), "r"(a[2]), "r"(a[3]), "r"(b[0]), "r"(b[1]));
}
__device__ __forceinline__ uint32_t packh(float lo, float hi) {
    uint32_t r;
    asm("cvt.rn.f16x2.f32 %0, %1, %2;" : "=r"(r) : "f"(hi), "f"(lo));
    return r;
}

// ---------------------------------------------------------------------------
// Launch 0: split x into fp16 hi/lo; block 0 additionally builds g_f / g_w
// ---------------------------------------------------------------------------
__global__ void split_x_setup(const float* __restrict__ s,
                              h16* __restrict__ hi, h16* __restrict__ lo, int n4,
                              const float* __restrict__ mu,
                              const float* __restrict__ lam,
                              const float* __restrict__ g1,
                              const float* __restrict__ g2,
                              const float* __restrict__ t1,
                              const float* __restrict__ t2)
{
    if (blockIdx.x == 0) {
        int tid = threadIdx.x;
        if (tid == 0) g_w = 1.f / (1.f + expf(-mu[0]));
        for (int idx = tid; idx < NH_ * 101; idx += blockDim.x) {
            int h = idx / 101, L = idx % 101;
            float Lf = (float)L;
            float val;
            if (h < 4) {
                float base = lam[h];
                float mag  = expf(Lf * logf(fabsf(base)));
                float sgn  = (base < 0.f) ? (1.f - 2.f * (float)(L & 1)) : 1.f;
                val = mag * sgn;
            } else if (h < 10) {
                int s2 = h - 4;
                val = expf(Lf * logf(g1[s2])) * sinf(t1[s2] * Lf);
            } else {
                int s2 = h - 10;
                val = expf(Lf * logf(g2[s2])) * cosf(t2[s2] * Lf);
            }
            g_f[h][L] = val;
        }
    }
    int i = blockIdx.x * blockDim.x + threadIdx.x;
    if (i >= n4) return;
    float4 a = ((const float4*)s)[i];
    float h0 = __half2float(__float2half_rn(a.x));
    float h1 = __half2float(__float2half_rn(a.y));
    float h2 = __half2float(__float2half_rn(a.z));
    float h3 = __half2float(__float2half_rn(a.w));
    uint2 H, L;
    H.x = packh(a.x, a.y);            H.y = packh(a.z, a.w);
    L.x = packh(a.x - h0, a.y - h1);  L.y = packh(a.z - h2, a.w - h3);
    ((uint2*)hi)[i] = H;
    ((uint2*)lo)[i] = L;
}

// ---------------------------------------------------------------------------
// Launch 1: all four weight conversions in one kernel (y = 0..3)
// y<3: Wq/Wk/Wv -> hi/lo split; y==3: Wf -> single fp16
// ---------------------------------------------------------------------------
__global__ void wsplit4(const float* __restrict__ Wq, const float* __restrict__ Wk,
                        const float* __restrict__ Wv, const float* __restrict__ Wf,
                        h16* __restrict__ Wh, h16* __restrict__ Wl,
                        h16* __restrict__ Wf1, int n4)
{
    int i = blockIdx.x * blockDim.x + threadIdx.x;
    if (i >= n4) return;
    const int z = blockIdx.y;
    const float* src = (z == 0) ? Wq : (z == 1) ? Wk : (z == 2) ? Wv : Wf;
    float4 a = ((const float4*)src)[i];
    if (z < 3) {
        const size_t WN = (size_t)D_ * D_;
        float h0 = __half2float(__float2half_rn(a.x));
        float h1 = __half2float(__float2half_rn(a.y));
        float h2 = __half2float(__float2half_rn(a.z));
        float h3 = __half2float(__float2half_rn(a.w));
        uint2 H, L;
        H.x = packh(a.x, a.y);            H.y = packh(a.z, a.w);
        L.x = packh(a.x - h0, a.y - h1);  L.y = packh(a.z - h2, a.w - h3);
        ((uint2*)(Wh + z * WN))[i] = H;
        ((uint2*)(Wl + z * WN))[i] = L;
    } else {
        uint2 H;
        H.x = packh(a.x, a.y);  H.y = packh(a.z, a.w);
        ((uint2*)Wf1)[i] = H;
    }
}

// ---------------------------------------------------------------------------
// Fused QKV NT GEMM (3-term fp16 split)
// grid (64, 8, 3): z picks {Q, K, V}. CTA 128x128, BK=32, 8 warps
// ---------------------------------------------------------------------------
constexpr int GL   = 40;
constexpr int GTB  = 128 * GL * 2;         // 10240 B per tile
constexpr int GBUF3 = 4 * GTB;
constexpr int GSMEM3 = 2 * GBUF3;          // 81920

__global__ void __launch_bounds__(256)
qkv_gemm(const h16* __restrict__ xh, const h16* __restrict__ xl,
         const h16* __restrict__ W0h, const h16* __restrict__ W0l,
         const h16* __restrict__ W1h, const h16* __restrict__ W1l,
         const h16* __restrict__ W2h, const h16* __restrict__ W2l,
         const float* __restrict__ b0, const float* __restrict__ b1,
         const float* __restrict__ b2,
         h16* __restrict__ Qh, h16* __restrict__ Ql,
         h16* __restrict__ Kh, h16* __restrict__ Kl,
         float* __restrict__ Vf, h16* __restrict__ V1)
{
    extern __shared__ char sm[];
    const uint32_t su = smem_u32(sm);
    const int tid = threadIdx.x;
    const int wid = tid >> 5, lane = tid & 31;
    const int wm = wid & 1, wn = wid >> 1;
    const int m0 = blockIdx.x * 128, n0 = blockIdx.y * 128;
    const int z = blockIdx.z;

    const h16* Bh = (z == 0) ? W0h : (z == 1) ? W1h : W2h;
    const h16* Bl = (z == 0) ? W0l : (z == 1) ? W1l : W2l;
    const float* bias = (z == 0) ? b0 : (z == 1) ? b1 : b2;

    const h16* srcs[4] = { xh + (size_t)m0 * D_, xl + (size_t)m0 * D_,
                           Bh + (size_t)n0 * D_, Bl + (size_t)n0 * D_ };

    const int lrow = lane & 15, lcol8 = (lane >> 4) * 8;
    const int g = lane >> 2, tg = lane & 3;

    auto load_chunk = [&](int c, int buf) {
        const int k0 = c * 32;
#pragma unroll
        for (int t = 0; t < 4; t++)
#pragma unroll
            for (int r = 0; r < 2; r++) {
                int id = r * 256 + tid;
                int row = id >> 2, q = id & 3;
                CP16(su + buf * GBUF3 + t * GTB + row * 80 + q * 16,
                     srcs[t] + (size_t)row * D_ + k0 + q * 8);
            }
    };

    load_chunk(0, 0); CP_COMMIT();

    float acc[4][4][4] = {};

    for (int c = 0; c < 32; c++) {
        if (c < 31) { load_chunk(c + 1, (c + 1) & 1); CP_COMMIT(); CP_WAIT(1); }
        else        { CP_WAIT(0); }
        __syncthreads();
        const uint32_t base = su + (c & 1) * GBUF3;
#pragma unroll
        for (int k2 = 0; k2 < 2; k2++) {
            const int kc = k2 * 16 + lcol8;
            uint32_t ah[4][4], al[4][4];
#pragma unroll
            for (int mt = 0; mt < 4; mt++) {
                uint32_t ar = base + ((wm * 64 + mt * 16 + lrow) * GL + kc) * 2;
                ldsm4(ah[mt][0], ah[mt][1], ah[mt][2], ah[mt][3], ar);
                ldsm4(al[mt][0], al[mt][1], al[mt][2], al[mt][3], ar + GTB);
            }
            uint32_t bh[4][2], bl[4][2];
#pragma unroll
            for (int np = 0; np < 2; np++) {
                uint32_t br = base + 2 * GTB + ((wn * 32 + np * 16 + lrow) * GL + kc) * 2;
                uint32_t r0, r1, r2, r3;
                ldsm4(r0, r1, r2, r3, br);
                bh[2*np][0] = r0; bh[2*np][1] = r2;
                bh[2*np+1][0] = r1; bh[2*np+1][1] = r3;
                ldsm4(r0, r1, r2, r3, br + GTB);
                bl[2*np][0] = r0; bl[2*np][1] = r2;
                bl[2*np+1][0] = r1; bl[2*np+1][1] = r3;
            }
#pragma unroll
            for (int mt = 0; mt < 4; mt++)
#pragma unroll
                for (int nt = 0; nt < 4; nt++) {
                    mma16816(acc[mt][nt], ah[mt], bh[nt]);
                    mma16816(acc[mt][nt], ah[mt], bl[nt]);
                    mma16816(acc[mt][nt], al[mt], bh[nt]);
                }
        }
        __syncthreads();
    }

    h16* Ch = (z == 0) ? Qh : Kh;
    h16* Cl = (z == 0) ? Ql : Kl;
#pragma unroll
    for (int mt = 0; mt < 4; mt++)
#pragma unroll
        for (int nt = 0; nt < 4; nt++) {
            const int col = n0 + wn * 32 + nt * 8 + tg * 2;
            const float b0v = bias[col], b1v = bias[col + 1];
#pragma unroll
            for (int hf = 0; hf < 2; hf++) {
                const int row = m0 + wm * 64 + mt * 16 + g + hf * 8;
                float v0 = acc[mt][nt][hf * 2]     + b0v;
                float v1 = acc[mt][nt][hf * 2 + 1] + b1v;
                if (z == 2) {
                    float2 o; o.x = v0; o.y = v1;
                    *(float2*)(Vf + (size_t)row * D_ + col) = o;
                    *(uint32_t*)(V1 + (size_t)row * D_ + col) = packh(v0, v1);
                } else {
                    float h0 = __half2float(__float2half_rn(v0));
                    float h1 = __half2float(__float2half_rn(v1));
                    *(uint32_t*)(Ch + (size_t)row * D_ + col) = packh(v0, v1);
                    *(uint32_t*)(Cl + (size_t)row * D_ + col) = packh(v0 - h0, v1 - h1);
                }
            }
        }
}

// ---------------------------------------------------------------------------
// HMMA flash attention (launch #3 -> gets profiled)
// ---------------------------------------------------------------------------
constexpr int AL   = 72;
constexpr int AQT  = 128 * AL * 2;
constexpr int AKT  = 64 * AL * 2;
constexpr int AKV  = 3 * AKT;
constexpr int ASM  = 2 * AQT + 2 * AKV;    // 92160

__global__ void __launch_bounds__(256)
attn_mma(const h16* __restrict__ Qh, const h16* __restrict__ Ql,
         const h16* __restrict__ Kh, const h16* __restrict__ Kl,
         const h16* __restrict__ V1, float* __restrict__ Mout)
{
    extern __shared__ char sm[];
    const uint32_t su = smem_u32(sm);
    const int tid = threadIdx.x;
    const int w = tid >> 5, lane = tid & 31;
    const int b = blockIdx.z, h = blockIdx.y, qt = blockIdx.x;
    const size_t tokQ = (size_t)b * T_ + qt * 128;
    const int lrow = lane & 15, lcol8 = (lane >> 4) * 8;
    const int g = lane >> 2, tg = lane & 3;
    const int i4 = lane >> 3, r8 = lane & 7;

    {
        const h16* qs[2] = { Qh, Ql };
#pragma unroll
        for (int t = 0; t < 2; t++)
#pragma unroll
            for (int r = 0; r < 4; r++) {
                int id = r * 256 + tid;
                int row = id >> 3, q = id & 7;
                CP16(su + t * AQT + row * (AL * 2) + q * 16,
                     qs[t] + (tokQ + row) * D_ + h * HC_ + q * 8);
            }
    }
    const h16* kvs[3] = { Kh, Kl, V1 };
    auto load_kv = [&](int kt, int buf) {
        const size_t tok = (size_t)b * T_ + kt * 64;
#pragma unroll
        for (int t = 0; t < 3; t++)
#pragma unroll
            for (int r = 0; r < 2; r++) {
                int id = r * 256 + tid;
                int row = id >> 3, q = id & 7;
                CP16(su + 2 * AQT + buf * AKV + t * AKT + row * (AL * 2) + q * 16,
                     kvs[t] + (tok + row) * D_ + h * HC_ + q * 8);
            }
    };
    load_kv(0, 0); CP_COMMIT();

    float o[8][4] = {};
    float m0r = -1e30f, m1r = -1e30f, l0 = 0.f, l1 = 0.f;

    const int NKT = T_ / 64;   // 32
    for (int kt = 0; kt < NKT; kt++) {
        if (kt < NKT - 1) { load_kv(kt + 1, (kt + 1) & 1); CP_COMMIT(); CP_WAIT(1); }
        else              { CP_WAIT(0); }
        __syncthreads();
        const uint32_t kv = su + 2 * AQT + (kt & 1) * AKV;

        // ---- S = Q K^T (3-term fp16 split) ----
        float sc[8][4] = {};
#pragma unroll
        for (int kk = 0; kk < 4; kk++) {
            const int kc = kk * 16 + lcol8;
            uint32_t aq[4], aql[4];
            {
                uint32_t ar = su + ((w * 16 + lrow) * AL + kc) * 2;
                ldsm4(aq[0], aq[1], aq[2], aq[3], ar);
                ldsm4(aql[0], aql[1], aql[2], aql[3], ar + AQT);
            }
            uint32_t bh[8][2], bl[8][2];
#pragma unroll
            for (int np = 0; np < 4; np++) {
                uint32_t br = kv + ((np * 16 + lrow) * AL + kc) * 2;
                uint32_t r0, r1, r2, r3;
                ldsm4(r0, r1, r2, r3, br);
                bh[2*np][0] = r0; bh[2*np][1] = r2;
                bh[2*np+1][0] = r1; bh[2*np+1][1] = r3;
                ldsm4(r0, r1, r2, r3, br + AKT);
                bl[2*np][0] = r0; bl[2*np][1] = r2;
                bl[2*np+1][0] = r1; bl[2*np+1][1] = r3;
            }
#pragma unroll
            for (int nt = 0; nt < 8; nt++) {
                mma16816(sc[nt], aq, bh[nt]);
                mma16816(sc[nt], aq, bl[nt]);
                mma16816(sc[nt], aql, bh[nt]);
            }
        }

        // ---- online softmax ----
        float mx0 = -1e30f, mx1 = -1e30f;
#pragma unroll
        for (int nt = 0; nt < 8; nt++) {
            mx0 = fmaxf(mx0, fmaxf(sc[nt][0], sc[nt][1]));
            mx1 = fmaxf(mx1, fmaxf(sc[nt][2], sc[nt][3]));
        }
        mx0 = fmaxf(mx0, __shfl_xor_sync(0xffffffffu, mx0, 1));
        mx0 = fmaxf(mx0, __shfl_xor_sync(0xffffffffu, mx0, 2));
        mx1 = fmaxf(mx1, __shfl_xor_sync(0xffffffffu, mx1, 1));
        mx1 = fmaxf(mx1, __shfl_xor_sync(0xffffffffu, mx1, 2));
        const float mn0 = fmaxf(m0r, mx0), mn1 = fmaxf(m1r, mx1);
        const float s0 = __expf(m0r - mn0), s1 = __expf(m1r - mn1);
        m0r = mn0; m1r = mn1;
        float sum0 = 0.f, sum1 = 0.f;
#pragma unroll
        for (int nt = 0; nt < 8; nt++) {
            sc[nt][0] = __expf(sc[nt][0] - mn0);
            sc[nt][1] = __expf(sc[nt][1] - mn0);
            sc[nt][2] = __expf(sc[nt][2] - mn1);
            sc[nt][3] = __expf(sc[nt][3] - mn1);
            sum0 += sc[nt][0] + sc[nt][1];
            sum1 += sc[nt][2] + sc[nt][3];
            o[nt][0] *= s0; o[nt][1] *= s0;
            o[nt][2] *= s1; o[nt][3] *= s1;
        }
        sum0 += __shfl_xor_sync(0xffffffffu, sum0, 1);
        sum0 += __shfl_xor_sync(0xffffffffu, sum0, 2);
        sum1 += __shfl_xor_sync(0xffffffffu, sum1, 1);
        sum1 += __shfl_xor_sync(0xffffffffu, sum1, 2);
        l0 = l0 * s0 + sum0;
        l1 = l1 * s1 + sum1;

        // ---- O += P V ----
#pragma unroll
        for (int kk = 0; kk < 4; kk++) {
            uint32_t ph[4];
            ph[0] = packh(sc[2*kk][0],   sc[2*kk][1]);
            ph[1] = packh(sc[2*kk][2],   sc[2*kk][3]);
            ph[2] = packh(sc[2*kk+1][0], sc[2*kk+1][1]);
            ph[3] = packh(sc[2*kk+1][2], sc[2*kk+1][3]);

            uint32_t vh[8][2];
#pragma unroll
            for (int np = 0; np < 4; np++) {
                int krow = kk * 16 + (i4 & 1) * 8 + r8;
                int ncol = np * 16 + (i4 >> 1) * 8;
                uint32_t vr = kv + 2 * AKT + (krow * AL + ncol) * 2;
                uint32_t r0, r1, r2, r3;
                ldsm4t(r0, r1, r2, r3, vr);
                vh[2*np][0] = r0; vh[2*np][1] = r1;
                vh[2*np+1][0] = r2; vh[2*np+1][1] = r3;
            }
#pragma unroll
            for (int nt = 0; nt < 8; nt++)
                mma16816(o[nt], ph, vh[nt]);
        }
        __syncthreads();
    }

    const float wgt = 1.f - g_w;
    const float i0 = wgt / l0, i1 = wgt / l1;
    const size_t row0 = tokQ + w * 16 + g;
    float* Mp0 = Mout + row0 * D_ + h * HC_;
    float* Mp1 = Mout + (row0 + 8) * D_ + h * HC_;
#pragma unroll
    for (int nt = 0; nt < 8; nt++) {
        float2 v0; v0.x = o[nt][0] * i0; v0.y = o[nt][1] * i0;
        float2 v1; v1.x = o[nt][2] * i1; v1.y = o[nt][3] * i1;
        *(float2*)(Mp0 + nt * 8 + tg * 2) = v0;
        *(float2*)(Mp1 + nt * 8 + tg * 2) = v1;
    }
}

// ---------------------------------------------------------------------------
// Output projection NT GEMM (2-term: M hi/lo x Wf single)
// ---------------------------------------------------------------------------
constexpr int GBUF2 = 3 * GTB;
constexpr int GSMEM2 = 2 * GBUF2;          // 61440

__global__ void __launch_bounds__(256)
out_gemm(const h16* __restrict__ Ah, const h16* __restrict__ Al,
         const h16* __restrict__ Bs, const float* __restrict__ bias,
         float* __restrict__ Cf)
{
    extern __shared__ char sm[];
    const uint32_t su = smem_u32(sm);
    const int tid = threadIdx.x;
    const int wid = tid >> 5, lane = tid & 31;
    const int wm = wid & 1, wn = wid >> 1;
    const int m0 = blockIdx.x * 128, n0 = blockIdx.y * 128;

    const h16* srcs[3] = { Ah + (size_t)m0 * D_, Al + (size_t)m0 * D_,
                           Bs + (size_t)n0 * D_ };

    const int lrow = lane & 15, lcol8 = (lane >> 4) * 8;
    const int g = lane >> 2, tg = lane & 3;

    auto load_chunk = [&](int c, int buf) {
        const int k0 = c * 32;
#pragma unroll
        for (int t = 0; t < 3; t++)
#pragma unroll
            for (int r = 0; r < 2; r++) {
                int id = r * 256 + tid;
                int row = id >> 2, q = id & 3;
                CP16(su + buf * GBUF2 + t * GTB + row * 80 + q * 16,
                     srcs[t] + (size_t)row * D_ + k0 + q * 8);
            }
    };

    load_chunk(0, 0); CP_COMMIT();

    float acc[4][4][4] = {};

    for (int c = 0; c < 32; c++) {
        if (c < 31) { load_chunk(c + 1, (c + 1) & 1); CP_COMMIT(); CP_WAIT(1); }
        else        { CP_WAIT(0); }
        __syncthreads();
        const uint32_t base = su + (c & 1) * GBUF2;
#pragma unroll
        for (int k2 = 0; k2 < 2; k2++) {
            const int kc = k2 * 16 + lcol8;
            uint32_t ah[4][4], al[4][4];
#pragma unroll
            for (int mt = 0; mt < 4; mt++) {
                uint32_t ar = base + ((wm * 64 + mt * 16 + lrow) * GL + kc) * 2;
                ldsm4(ah[mt][0], ah[mt][1], ah[mt][2], ah[mt][3], ar);
                ldsm4(al[mt][0], al[mt][1], al[mt][2], al[mt][3], ar + GTB);
            }
            uint32_t bh[4][2];
#pragma unroll
            for (int np = 0; np < 2; np++) {
                uint32_t br = base + 2 * GTB + ((wn * 32 + np * 16 + lrow) * GL + kc) * 2;
                uint32_t r0, r1, r2, r3;
                ldsm4(r0, r1, r2, r3, br);
                bh[2*np][0] = r0; bh[2*np][1] = r2;
                bh[2*np+1][0] = r1; bh[2*np+1][1] = r3;
            }
#pragma unroll
            for (int mt = 0; mt < 4; mt++)
#pragma unroll
                for (int nt = 0; nt < 4; nt++) {
                    mma16816(acc[mt][nt], ah[mt], bh[nt]);
                    mma16816(acc[mt][nt], al[mt], bh[nt]);
                }
        }
        __syncthreads();
    }

#pragma unroll
    for (int mt = 0; mt < 4; mt++)
#pragma unroll
        for (int nt = 0; nt < 4; nt++) {
            const int col = n0 + wn * 32 + nt * 8 + tg * 2;
            const float b0v = bias[col], b1v = bias[col + 1];
#pragma unroll
            for (int hf = 0; hf < 2; hf++) {
                const int row = m0 + wm * 64 + mt * 16 + g + hf * 8;
                float2 o;
                o.x = acc[mt][nt][hf * 2]     + b0v;
                o.y = acc[mt][nt][hf * 2 + 1] + b1v;
                *(float2*)(Cf + (size_t)row * D_ + col) = o;
            }
        }
}

// ---------------------------------------------------------------------------
// Parallel prefix sums of V along t (segmented two-pass)
// ---------------------------------------------------------------------------
__global__ void prefA(const float* __restrict__ V, float* __restrict__ part)
{
    int idx = blockIdx.x * blockDim.x + threadIdx.x;   // 65536
    int d = idx & 1023, seg = (idx >> 10) & 15, b = idx >> 14;
    size_t base = ((size_t)(b * T_) + seg * 128) * D_ + d;
    float s = 0.f;
#pragma unroll 4
    for (int i = 0; i < 128; i++) s += V[base + (size_t)i * D_];
    part[(b * 16 + seg) * 1024 + d] = s;
}

__global__ void prefC(const float* __restrict__ V, const float* __restrict__ part,
                      float* __restrict__ PRE)
{
    int idx = blockIdx.x * blockDim.x + threadIdx.x;
    int d = idx & 1023, seg = (idx >> 10) & 15, b = idx >> 14;
    float off = 0.f;
    for (int s2 = 0; s2 < seg; s2++) off += part[(b * 16 + s2) * 1024 + d];
    size_t base = ((size_t)(b * T_) + seg * 128) * D_ + d;
    float s = off;
#pragma unroll 4
    for (int i = 0; i < 128; i++) {
        s += V[base + (size_t)i * D_];
        PRE[base + (size_t)i * D_] = s;
    }
}

// ---------------------------------------------------------------------------
// P@V window conv + blend + fp16 hi/lo split of the result (feeds out_gemm)
// ---------------------------------------------------------------------------
constexpr int PWS   = 237;
constexpr int PWSMEM = (104 + 64 * PWS) * 4;        // 61088 B

__global__ void __launch_bounds__(256)
pwin2(const float* __restrict__ V, const float* __restrict__ PRE,
      const float* __restrict__ M, h16* __restrict__ Mh, h16* __restrict__ Ml)
{
    extern __shared__ float ps[];
    float* fs = ps;               // [104]
    float* Vs = ps + 104;         // [64][237]

    const int tid = threadIdx.x;
    const int t0 = blockIdx.x * 128, h = blockIdx.y, b = blockIdx.z;

    if (tid < 101) fs[tid] = g_f[h][tid];
    for (int id = tid; id < 228 * 16; id += 256) {
        int r = id >> 4, q = id & 15;
        int t = t0 - 100 + r;
        float4 v = make_float4(0.f, 0.f, 0.f, 0.f);
        if (t >= 0)
            v = *(const float4*)(V + ((size_t)(b * T_) + t) * D_ + h * HC_ + q * 4);
        Vs[(q * 4 + 0) * PWS + r] = v.x;
        Vs[(q * 4 + 1) * PWS + r] = v.y;
        Vs[(q * 4 + 2) * PWS + r] = v.z;
        Vs[(q * 4 + 3) * PWS + r] = v.w;
    }
    __syncthreads();

    const int c = tid & 63, tq = tid >> 6;
    const float f100 = fs[100];
    const float wv = g_w;
    const float* vc = Vs + c * PWS;

#pragma unroll 1
    for (int s = 0; s < 8; s++) {
        const int tb = (tq + 4 * s) * 4;
        float a0 = 0.f, a1 = 0.f, a2 = 0.f, a3 = 0.f;
#pragma unroll 4
        for (int j = tb - 99; j <= tb + 2; j++) {
            float v = vc[j + 100];
            int d0 = tb - j;
            if (d0 >= 1 && d0 <= 99)     a0 += fs[d0] * v;
            if (d0 + 1 >= 1 && d0 + 1 <= 99) a1 += fs[d0 + 1] * v;
            if (d0 + 2 >= 1 && d0 + 2 <= 99) a2 += fs[d0 + 2] * v;
            if (d0 + 3 >= 1 && d0 + 3 <= 99) a3 += fs[d0 + 3] * v;
        }
        float acc[4] = { a0, a1, a2, a3 };
#pragma unroll
        for (int i = 0; i < 4; i++) {
            int t = t0 + tb + i;
            float a = acc[i];
            if (t >= 100)
                a += f100 * PRE[((size_t)(b * T_) + t - 100) * D_ + h * HC_ + c];
            size_t o = ((size_t)(b * T_) + t) * D_ + h * HC_ + c;
            float tot = M[o] + wv * a;
            float hh = __half2float(__float2half_rn(tot));
            Mh[o] = __float2half_rn(tot);
            Ml[o] = __float2half_rn(tot - hh);
        }
    }
}

// ---------------------------------------------------------------------------
// Launch
// ---------------------------------------------------------------------------
extern "C" void kernel_launch(void* const* d_in, const int* in_sizes, int n_in,
                              void* d_out, int out_size)
{
    const float* x   = (const float*)d_in[0];
    const float* mu  = (const float*)d_in[1];
    const float* lam = (const float*)d_in[2];
    const float* g1  = (const float*)d_in[3];
    const float* g2  = (const float*)d_in[4];
    const float* t1  = (const float*)d_in[5];
    const float* t2  = (const float*)d_in[6];
    const float* Wq  = (const float*)d_in[7];
    const float* bq  = (const float*)d_in[8];
    const float* Wk  = (const float*)d_in[9];
    const float* bk  = (const float*)d_in[10];
    const float* Wv  = (const float*)d_in[11];
    const float* bv  = (const float*)d_in[12];
    const float* Wf  = (const float*)d_in[13];
    const float* bf  = (const float*)d_in[14];
    float* out = (float*)d_out;

    float *Vb, *Mb, *PREb, *partb;
    cudaGetSymbolAddress((void**)&Vb,    g_V);
    cudaGetSymbolAddress((void**)&Mb,    g_M);
    cudaGetSymbolAddress((void**)&PREb,  g_PRE);
    cudaGetSymbolAddress((void**)&partb, g_part);
    h16 *xh, *xl, *Mh, *Ml, *Wh, *Wl, *Wf1, *Qh, *Ql, *Kh, *Kl, *V1;
    cudaGetSymbolAddress((void**)&xh,  g_xh);
    cudaGetSymbolAddress((void**)&xl,  g_xl);
    cudaGetSymbolAddress((void**)&Mh,  g_Mh);
    cudaGetSymbolAddress((void**)&Ml,  g_Ml);
    cudaGetSymbolAddress((void**)&Wh,  g_Wh);
    cudaGetSymbolAddress((void**)&Wl,  g_Wl);
    cudaGetSymbolAddress((void**)&Wf1, g_Wf1);
    cudaGetSymbolAddress((void**)&Qh,  g_Qh);
    cudaGetSymbolAddress((void**)&Ql,  g_Ql);
    cudaGetSymbolAddress((void**)&Kh,  g_Kh);
    cudaGetSymbolAddress((void**)&Kl,  g_Kl);
    cudaGetSymbolAddress((void**)&V1,  g_V1);

    cudaFuncSetAttribute(qkv_gemm,
                         cudaFuncAttributeMaxDynamicSharedMemorySize, GSMEM3);
    cudaFuncSetAttribute(out_gemm,
                         cudaFuncAttributeMaxDynamicSharedMemorySize, GSMEM2);
    cudaFuncSetAttribute(attn_mma,
                         cudaFuncAttributeMaxDynamicSharedMemorySize, ASM);
    cudaFuncSetAttribute(pwin2,
                         cudaFuncAttributeMaxDynamicSharedMemorySize, PWSMEM);

    const size_t WN = (size_t)D_ * D_;
    const int n4x = NTOK_ * D_ / 4, n4w = (int)(WN / 4);

    // launch 0: x split + setup table
    split_x_setup<<<(n4x + 255) / 256, 256>>>(x, xh, xl, n4x,
                                              mu, lam, g1, g2, t1, t2);
    // launch 1: all weight conversions
    wsplit4<<<dim3((n4w + 255) / 256, 4), 256>>>(Wq, Wk, Wv, Wf, Wh, Wl, Wf1, n4w);

    // launch 2: fused QKV projections
    dim3 tg(NTOK_ / 128, D_ / 128, 3);
    qkv_gemm<<<tg, 256, GSMEM3>>>(xh, xl,
                                  Wh + 0 * WN, Wl + 0 * WN,
                                  Wh + 1 * WN, Wl + 1 * WN,
                                  Wh + 2 * WN, Wl + 2 * WN,
                                  bq, bk, bv,
                                  Qh, Ql, Kh, Kl, Vb, V1);

    // launch 3: attention (profiled by ncu -s 5)
    dim3 agrid(T_ / 128, NH_, B_);
    attn_mma<<<agrid, 256, ASM>>>(Qh, Ql, Kh, Kl, V1, Mb);

    // launches 4-5: prefix sums (independent of attention)
    prefA<<<256, 256>>>(Vb, partb);
    prefC<<<256, 256>>>(Vb, partb, PREb);

    // launch 6: P-window conv + blend + split into Mh/Ml
    dim3 pgrid(T_ / 128, NH_, B_);
    pwin2<<<pgrid, 256, PWSMEM>>>(Vb, PREb, Mb, Mh, Ml);

    // launch 7: output projection
    dim3 og(NTOK_ / 128, D_ / 128);
    out_gemm<<<og, 256, GSMEM2>>>(Mh, Ml, Wf1, bf, out);
}

// round 6
// speedup vs baseline: 3.8435x; 1.0873x over previous
#include <cuda_runtime.h>
#include <cuda_fp16.h>
#include <math.h>
#include <cstdint>

using h16 = __half;

// ---------------------------------------------------------------------------
// Shapes
// ---------------------------------------------------------------------------
constexpr int B_    = 4;
constexpr int T_    = 2048;
constexpr int D_    = 1024;
constexpr int NH_   = 16;
constexpr int HC_   = 64;
constexpr int NTOK_ = B_ * T_;      // 8192

// ---------------------------------------------------------------------------
// Scratch (device globals)
// ---------------------------------------------------------------------------
__device__ float g_V  [(size_t)NTOK_ * D_];
__device__ float g_M  [(size_t)NTOK_ * D_];   // w * (P@V), then consumed by attn
__device__ float g_PRE[(size_t)NTOK_ * D_];
__device__ float g_part[4 * 16 * 1024];
__device__ float g_f[NH_][101];
__device__ float g_w;

__device__ h16 g_xh[(size_t)NTOK_ * D_];
__device__ h16 g_xl[(size_t)NTOK_ * D_];
__device__ h16 g_Mh[(size_t)NTOK_ * D_];      // fp16 blended M (single term)
__device__ h16 g_Wh[3][(size_t)D_ * D_];      // Wq, Wk, Wv hi
__device__ h16 g_Wl[3][(size_t)D_ * D_];      // Wq, Wk, Wv lo
__device__ h16 g_Wf1[(size_t)D_ * D_];        // Wf single fp16
__device__ h16 g_Qh[(size_t)NTOK_ * D_];
__device__ h16 g_Ql[(size_t)NTOK_ * D_];
__device__ h16 g_Kh[(size_t)NTOK_ * D_];
__device__ h16 g_Kl[(size_t)NTOK_ * D_];
__device__ h16 g_V1[(size_t)NTOK_ * D_];      // V single fp16

// ---------------------------------------------------------------------------
// PTX helpers (sm_80-era, valid on plain sm_103 target)
// ---------------------------------------------------------------------------
__device__ __forceinline__ uint32_t smem_u32(const void* p) {
    uint32_t a;
    asm("{ .reg .u64 t; cvta.to.shared.u64 t, %1; cvt.u32.u64 %0, t; }"
        : "=r"(a) : "l"(p));
    return a;
}
#define CP16(s, g) \
    asm volatile("cp.async.cg.shared.global [%0], [%1], 16;" \
                 :: "r"(s), "l"(g) : "memory")
#define CP_COMMIT() asm volatile("cp.async.commit_group;" ::: "memory")
#define CP_WAIT(n)  asm volatile("cp.async.wait_group %0;" :: "n"(n) : "memory")

__device__ __forceinline__ void ldsm4(uint32_t& r0, uint32_t& r1,
                                      uint32_t& r2, uint32_t& r3, uint32_t a) {
    asm volatile("ldmatrix.sync.aligned.m8n8.x4.shared.b16 {%0,%1,%2,%3}, [%4];"
                 : "=r"(r0), "=r"(r1), "=r"(r2), "=r"(r3) : "r"(a));
}
__device__ __forceinline__ void ldsm4t(uint32_t& r0, uint32_t& r1,
                                       uint32_t& r2, uint32_t& r3, uint32_t a) {
    asm volatile("ldmatrix.sync.aligned.m8n8.x4.trans.shared.b16 {%0,%1,%2,%3}, [%4];"
                 : "=r"(r0), "=r"(r1), "=r"(r2), "=r"(r3) : "r"(a));
}
__device__ __forceinline__ void mma16816(float* c, const uint32_t* a, const uint32_t* b) {
    asm volatile(
        "mma.sync.aligned.m16n8k16.row.col.f32.f16.f16.f32 "
        "{%0,%1,%2,%3},{%4,%5,%6,%7},{%8,%9},{%0,%1,%2,%3};"
        : "+f"(c[0]), "+f"(c[1]), "+f"(c[2]), "+f"(c[3])
        : "r"(a[0]), "r"(a[1]), "r"(a[2]), "r"(a[3]), "r"(b[0]), "r"(b[1]));
}
__device__ __forceinline__ uint32_t packh(float lo, float hi) {
    uint32_t r;
    asm("cvt.rn.f16x2.f32 %0, %1, %2;" : "=r"(r) : "f"(hi), "f"(lo));
    return r;
}

// ---------------------------------------------------------------------------
// Launch 0: split x into fp16 hi/lo; block 0 additionally builds g_f / g_w
// ---------------------------------------------------------------------------
__global__ void split_x_setup(const float* __restrict__ s,
                              h16* __restrict__ hi, h16* __restrict__ lo, int n4,
                              const float* __restrict__ mu,
                              const float* __restrict__ lam,
                              const float* __restrict__ g1,
                              const float* __restrict__ g2,
                              const float* __restrict__ t1,
                              const float* __restrict__ t2)
{
    if (blockIdx.x == 0) {
        int tid = threadIdx.x;
        if (tid == 0) g_w = 1.f / (1.f + expf(-mu[0]));
        for (int idx = tid; idx < NH_ * 101; idx += blockDim.x) {
            int h = idx / 101, L = idx % 101;
            float Lf = (float)L;
            float val;
            if (h < 4) {
                float base = lam[h];
                float mag  = expf(Lf * logf(fabsf(base)));
                float sgn  = (base < 0.f) ? (1.f - 2.f * (float)(L & 1)) : 1.f;
                val = mag * sgn;
            } else if (h < 10) {
                int s2 = h - 4;
                val = expf(Lf * logf(g1[s2])) * sinf(t1[s2] * Lf);
            } else {
                int s2 = h - 10;
                val = expf(Lf * logf(g2[s2])) * cosf(t2[s2] * Lf);
            }
            g_f[h][L] = val;
        }
    }
    int i = blockIdx.x * blockDim.x + threadIdx.x;
    if (i >= n4) return;
    float4 a = ((const float4*)s)[i];
    float h0 = __half2float(__float2half_rn(a.x));
    float h1 = __half2float(__float2half_rn(a.y));
    float h2 = __half2float(__float2half_rn(a.z));
    float h3 = __half2float(__float2half_rn(a.w));
    uint2 H, L;
    H.x = packh(a.x, a.y);            H.y = packh(a.z, a.w);
    L.x = packh(a.x - h0, a.y - h1);  L.y = packh(a.z - h2, a.w - h3);
    ((uint2*)hi)[i] = H;
    ((uint2*)lo)[i] = L;
}

// ---------------------------------------------------------------------------
// Launch 1: Wq/Wk/Wv hi/lo splits (z = 0..2)
// ---------------------------------------------------------------------------
__global__ void wsplit3(const float* __restrict__ Wq, const float* __restrict__ Wk,
                        const float* __restrict__ Wv,
                        h16* __restrict__ Wh, h16* __restrict__ Wl, int n4)
{
    int i = blockIdx.x * blockDim.x + threadIdx.x;
    if (i >= n4) return;
    const int z = blockIdx.y;
    const float* src = (z == 0) ? Wq : (z == 1) ? Wk : Wv;
    float4 a = ((const float4*)src)[i];
    const size_t WN = (size_t)D_ * D_;
    float h0 = __half2float(__float2half_rn(a.x));
    float h1 = __half2float(__float2half_rn(a.y));
    float h2 = __half2float(__float2half_rn(a.z));
    float h3 = __half2float(__float2half_rn(a.w));
    uint2 H, L;
    H.x = packh(a.x, a.y);            H.y = packh(a.z, a.w);
    L.x = packh(a.x - h0, a.y - h1);  L.y = packh(a.z - h2, a.w - h3);
    ((uint2*)(Wh + z * WN))[i] = H;
    ((uint2*)(Wl + z * WN))[i] = L;
}

// ---------------------------------------------------------------------------
// Launch 2: Wf -> single fp16
// ---------------------------------------------------------------------------
__global__ void wsplitF(const float* __restrict__ Wf, h16* __restrict__ Wf1, int n4)
{
    int i = blockIdx.x * blockDim.x + threadIdx.x;
    if (i >= n4) return;
    float4 a = ((const float4*)Wf)[i];
    uint2 H;
    H.x = packh(a.x, a.y);  H.y = packh(a.z, a.w);
    ((uint2*)Wf1)[i] = H;
}

// ---------------------------------------------------------------------------
// Launch 3 (PROFILED): fused QKV NT GEMM
// Q, K: 3-term fp16 split. V: 2-term (drops xl*Wvh; V linear, err ~2^-12)
// grid (64, 8, 3): z picks {Q, K, V}. CTA 128x128, BK=32, 8 warps
// ---------------------------------------------------------------------------
constexpr int GL   = 40;
constexpr int GTB  = 128 * GL * 2;         // 10240 B per tile
constexpr int GBUF3 = 4 * GTB;
constexpr int GSMEM3 = 2 * GBUF3;          // 81920

__global__ void __launch_bounds__(256)
qkv_gemm(const h16* __restrict__ xh, const h16* __restrict__ xl,
         const h16* __restrict__ W0h, const h16* __restrict__ W0l,
         const h16* __restrict__ W1h, const h16* __restrict__ W1l,
         const h16* __restrict__ W2h, const h16* __restrict__ W2l,
         const float* __restrict__ b0, const float* __restrict__ b1,
         const float* __restrict__ b2,
         h16* __restrict__ Qh, h16* __restrict__ Ql,
         h16* __restrict__ Kh, h16* __restrict__ Kl,
         float* __restrict__ Vf, h16* __restrict__ V1)
{
    extern __shared__ char sm[];
    const uint32_t su = smem_u32(sm);
    const int tid = threadIdx.x;
    const int wid = tid >> 5, lane = tid & 31;
    const int wm = wid & 1, wn = wid >> 1;
    const int m0 = blockIdx.x * 128, n0 = blockIdx.y * 128;
    const int z = blockIdx.z;
    const bool isV = (z == 2);

    const h16* Bh = (z == 0) ? W0h : (z == 1) ? W1h : W2h;
    const h16* Bl = (z == 0) ? W0l : (z == 1) ? W1l : W2l;
    const float* bias = (z == 0) ? b0 : (z == 1) ? b1 : b2;

    const h16* srcs[4] = { xh + (size_t)m0 * D_, xl + (size_t)m0 * D_,
                           Bh + (size_t)n0 * D_, Bl + (size_t)n0 * D_ };

    const int lrow = lane & 15, lcol8 = (lane >> 4) * 8;
    const int g = lane >> 2, tg = lane & 3;

    auto load_chunk = [&](int c, int buf) {
        const int k0 = c * 32;
#pragma unroll
        for (int t = 0; t < 4; t++)
#pragma unroll
            for (int r = 0; r < 2; r++) {
                int id = r * 256 + tid;
                int row = id >> 2, q = id & 3;
                CP16(su + buf * GBUF3 + t * GTB + row * 80 + q * 16,
                     srcs[t] + (size_t)row * D_ + k0 + q * 8);
            }
    };

    load_chunk(0, 0); CP_COMMIT();

    float acc[4][4][4] = {};

    for (int c = 0; c < 32; c++) {
        if (c < 31) { load_chunk(c + 1, (c + 1) & 1); CP_COMMIT(); CP_WAIT(1); }
        else        { CP_WAIT(0); }
        __syncthreads();
        const uint32_t base = su + (c & 1) * GBUF3;
#pragma unroll
        for (int k2 = 0; k2 < 2; k2++) {
            const int kc = k2 * 16 + lcol8;
            uint32_t ah[4][4], al[4][4];
#pragma unroll
            for (int mt = 0; mt < 4; mt++) {
                uint32_t ar = base + ((wm * 64 + mt * 16 + lrow) * GL + kc) * 2;
                ldsm4(ah[mt][0], ah[mt][1], ah[mt][2], ah[mt][3], ar);
                ldsm4(al[mt][0], al[mt][1], al[mt][2], al[mt][3], ar + GTB);
            }
            uint32_t bh[4][2], bl[4][2];
#pragma unroll
            for (int np = 0; np < 2; np++) {
                uint32_t br = base + 2 * GTB + ((wn * 32 + np * 16 + lrow) * GL + kc) * 2;
                uint32_t r0, r1, r2, r3;
                ldsm4(r0, r1, r2, r3, br);
                bh[2*np][0] = r0; bh[2*np][1] = r2;
                bh[2*np+1][0] = r1; bh[2*np+1][1] = r3;
                ldsm4(r0, r1, r2, r3, br + GTB);
                bl[2*np][0] = r0; bl[2*np][1] = r2;
                bl[2*np+1][0] = r1; bl[2*np+1][1] = r3;
            }
#pragma unroll
            for (int mt = 0; mt < 4; mt++)
#pragma unroll
                for (int nt = 0; nt < 4; nt++) {
                    mma16816(acc[mt][nt], ah[mt], bh[nt]);
                    mma16816(acc[mt][nt], ah[mt], bl[nt]);
                }
            if (!isV) {
#pragma unroll
                for (int mt = 0; mt < 4; mt++)
#pragma unroll
                    for (int nt = 0; nt < 4; nt++)
                        mma16816(acc[mt][nt], al[mt], bh[nt]);
            }
        }
        __syncthreads();
    }

    h16* Ch = (z == 0) ? Qh : Kh;
    h16* Cl = (z == 0) ? Ql : Kl;
#pragma unroll
    for (int mt = 0; mt < 4; mt++)
#pragma unroll
        for (int nt = 0; nt < 4; nt++) {
            const int col = n0 + wn * 32 + nt * 8 + tg * 2;
            const float b0v = bias[col], b1v = bias[col + 1];
#pragma unroll
            for (int hf = 0; hf < 2; hf++) {
                const int row = m0 + wm * 64 + mt * 16 + g + hf * 8;
                float v0 = acc[mt][nt][hf * 2]     + b0v;
                float v1 = acc[mt][nt][hf * 2 + 1] + b1v;
                if (isV) {
                    float2 o; o.x = v0; o.y = v1;
                    *(float2*)(Vf + (size_t)row * D_ + col) = o;
                    *(uint32_t*)(V1 + (size_t)row * D_ + col) = packh(v0, v1);
                } else {
                    float h0 = __half2float(__float2half_rn(v0));
                    float h1 = __half2float(__float2half_rn(v1));
                    *(uint32_t*)(Ch + (size_t)row * D_ + col) = packh(v0, v1);
                    *(uint32_t*)(Cl + (size_t)row * D_ + col) = packh(v0 - h0, v1 - h1);
                }
            }
        }
}

// ---------------------------------------------------------------------------
// Parallel prefix sums of V along t (segmented two-pass)
// ---------------------------------------------------------------------------
__global__ void prefA(const float* __restrict__ V, float* __restrict__ part)
{
    int idx = blockIdx.x * blockDim.x + threadIdx.x;   // 65536
    int d = idx & 1023, seg = (idx >> 10) & 15, b = idx >> 14;
    size_t base = ((size_t)(b * T_) + seg * 128) * D_ + d;
    float s = 0.f;
#pragma unroll 4
    for (int i = 0; i < 128; i++) s += V[base + (size_t)i * D_];
    part[(b * 16 + seg) * 1024 + d] = s;
}

__global__ void prefC(const float* __restrict__ V, const float* __restrict__ part,
                      float* __restrict__ PRE)
{
    int idx = blockIdx.x * blockDim.x + threadIdx.x;
    int d = idx & 1023, seg = (idx >> 10) & 15, b = idx >> 14;
    float off = 0.f;
    for (int s2 = 0; s2 < seg; s2++) off += part[(b * 16 + s2) * 1024 + d];
    size_t base = ((size_t)(b * T_) + seg * 128) * D_ + d;
    float s = off;
#pragma unroll 4
    for (int i = 0; i < 128; i++) {
        s += V[base + (size_t)i * D_];
        PRE[base + (size_t)i * D_] = s;
    }
}

// ---------------------------------------------------------------------------
// P@V window conv: writes M = w * (P@V)   (pure write; attn adds its part)
// ---------------------------------------------------------------------------
constexpr int PWS   = 237;
constexpr int PWSMEM = (104 + 64 * PWS) * 4;        // 61088 B

__global__ void __launch_bounds__(256)
pwin2(const float* __restrict__ V, const float* __restrict__ PRE,
      float* __restrict__ M)
{
    extern __shared__ float ps[];
    float* fs = ps;               // [104]
    float* Vs = ps + 104;         // [64][237]

    const int tid = threadIdx.x;
    const int t0 = blockIdx.x * 128, h = blockIdx.y, b = blockIdx.z;

    if (tid < 101) fs[tid] = g_f[h][tid];
    for (int id = tid; id < 228 * 16; id += 256) {
        int r = id >> 4, q = id & 15;
        int t = t0 - 100 + r;
        float4 v = make_float4(0.f, 0.f, 0.f, 0.f);
        if (t >= 0)
            v = *(const float4*)(V + ((size_t)(b * T_) + t) * D_ + h * HC_ + q * 4);
        Vs[(q * 4 + 0) * PWS + r] = v.x;
        Vs[(q * 4 + 1) * PWS + r] = v.y;
        Vs[(q * 4 + 2) * PWS + r] = v.z;
        Vs[(q * 4 + 3) * PWS + r] = v.w;
    }
    __syncthreads();

    const int c = tid & 63, tq = tid >> 6;
    const float f100 = fs[100];
    const float wv = g_w;
    const float* vc = Vs + c * PWS;

#pragma unroll 1
    for (int s = 0; s < 8; s++) {
        const int tb = (tq + 4 * s) * 4;
        float a0 = 0.f, a1 = 0.f, a2 = 0.f, a3 = 0.f;
#pragma unroll 4
        for (int j = tb - 99; j <= tb + 2; j++) {
            float v = vc[j + 100];
            int d0 = tb - j;
            if (d0 >= 1 && d0 <= 99)     a0 += fs[d0] * v;
            if (d0 + 1 >= 1 && d0 + 1 <= 99) a1 += fs[d0 + 1] * v;
            if (d0 + 2 >= 1 && d0 + 2 <= 99) a2 += fs[d0 + 2] * v;
            if (d0 + 3 >= 1 && d0 + 3 <= 99) a3 += fs[d0 + 3] * v;
        }
        float acc[4] = { a0, a1, a2, a3 };
#pragma unroll
        for (int i = 0; i < 4; i++) {
            int t = t0 + tb + i;
            float a = acc[i];
            if (t >= 100)
                a += f100 * PRE[((size_t)(b * T_) + t - 100) * D_ + h * HC_ + c];
            M[((size_t)(b * T_) + t) * D_ + h * HC_ + c] = wv * a;
        }
    }
}

// ---------------------------------------------------------------------------
// HMMA flash attention; epilogue blends with w*PV (from Min) and emits fp16 Mh
// ---------------------------------------------------------------------------
constexpr int AL   = 72;
constexpr int AQT  = 128 * AL * 2;
constexpr int AKT  = 64 * AL * 2;
constexpr int AKV  = 3 * AKT;
constexpr int ASM  = 2 * AQT + 2 * AKV;    // 92160

__global__ void __launch_bounds__(256)
attn_mma(const h16* __restrict__ Qh, const h16* __restrict__ Ql,
         const h16* __restrict__ Kh, const h16* __restrict__ Kl,
         const h16* __restrict__ V1, const float* __restrict__ Min,
         h16* __restrict__ Mh)
{
    extern __shared__ char sm[];
    const uint32_t su = smem_u32(sm);
    const int tid = threadIdx.x;
    const int w = tid >> 5, lane = tid & 31;
    const int b = blockIdx.z, h = blockIdx.y, qt = blockIdx.x;
    const size_t tokQ = (size_t)b * T_ + qt * 128;
    const int lrow = lane & 15, lcol8 = (lane >> 4) * 8;
    const int g = lane >> 2, tg = lane & 3;
    const int i4 = lane >> 3, r8 = lane & 7;

    {
        const h16* qs[2] = { Qh, Ql };
#pragma unroll
        for (int t = 0; t < 2; t++)
#pragma unroll
            for (int r = 0; r < 4; r++) {
                int id = r * 256 + tid;
                int row = id >> 3, q = id & 7;
                CP16(su + t * AQT + row * (AL * 2) + q * 16,
                     qs[t] + (tokQ + row) * D_ + h * HC_ + q * 8);
            }
    }
    const h16* kvs[3] = { Kh, Kl, V1 };
    auto load_kv = [&](int kt, int buf) {
        const size_t tok = (size_t)b * T_ + kt * 64;
#pragma unroll
        for (int t = 0; t < 3; t++)
#pragma unroll
            for (int r = 0; r < 2; r++) {
                int id = r * 256 + tid;
                int row = id >> 3, q = id & 7;
                CP16(su + 2 * AQT + buf * AKV + t * AKT + row * (AL * 2) + q * 16,
                     kvs[t] + (tok + row) * D_ + h * HC_ + q * 8);
            }
    };
    load_kv(0, 0); CP_COMMIT();

    float o[8][4] = {};
    float m0r = -1e30f, m1r = -1e30f, l0 = 0.f, l1 = 0.f;

    const int NKT = T_ / 64;   // 32
    for (int kt = 0; kt < NKT; kt++) {
        if (kt < NKT - 1) { load_kv(kt + 1, (kt + 1) & 1); CP_COMMIT(); CP_WAIT(1); }
        else              { CP_WAIT(0); }
        __syncthreads();
        const uint32_t kv = su + 2 * AQT + (kt & 1) * AKV;

        // ---- S = Q K^T (3-term fp16 split) ----
        float sc[8][4] = {};
#pragma unroll
        for (int kk = 0; kk < 4; kk++) {
            const int kc = kk * 16 + lcol8;
            uint32_t aq[4], aql[4];
            {
                uint32_t ar = su + ((w * 16 + lrow) * AL + kc) * 2;
                ldsm4(aq[0], aq[1], aq[2], aq[3], ar);
                ldsm4(aql[0], aql[1], aql[2], aql[3], ar + AQT);
            }
            uint32_t bh[8][2], bl[8][2];
#pragma unroll
            for (int np = 0; np < 4; np++) {
                uint32_t br = kv + ((np * 16 + lrow) * AL + kc) * 2;
                uint32_t r0, r1, r2, r3;
                ldsm4(r0, r1, r2, r3, br);
                bh[2*np][0] = r0; bh[2*np][1] = r2;
                bh[2*np+1][0] = r1; bh[2*np+1][1] = r3;
                ldsm4(r0, r1, r2, r3, br + AKT);
                bl[2*np][0] = r0; bl[2*np][1] = r2;
                bl[2*np+1][0] = r1; bl[2*np+1][1] = r3;
            }
#pragma unroll
            for (int nt = 0; nt < 8; nt++) {
                mma16816(sc[nt], aq, bh[nt]);
                mma16816(sc[nt], aq, bl[nt]);
                mma16816(sc[nt], aql, bh[nt]);
            }
        }

        // ---- online softmax ----
        float mx0 = -1e30f, mx1 = -1e30f;
#pragma unroll
        for (int nt = 0; nt < 8; nt++) {
            mx0 = fmaxf(mx0, fmaxf(sc[nt][0], sc[nt][1]));
            mx1 = fmaxf(mx1, fmaxf(sc[nt][2], sc[nt][3]));
        }
        mx0 = fmaxf(mx0, __shfl_xor_sync(0xffffffffu, mx0, 1));
        mx0 = fmaxf(mx0, __shfl_xor_sync(0xffffffffu, mx0, 2));
        mx1 = fmaxf(mx1, __shfl_xor_sync(0xffffffffu, mx1, 1));
        mx1 = fmaxf(mx1, __shfl_xor_sync(0xffffffffu, mx1, 2));
        const float mn0 = fmaxf(m0r, mx0), mn1 = fmaxf(m1r, mx1);
        const float s0 = __expf(m0r - mn0), s1 = __expf(m1r - mn1);
        m0r = mn0; m1r = mn1;
        float sum0 = 0.f, sum1 = 0.f;
#pragma unroll
        for (int nt = 0; nt < 8; nt++) {
            sc[nt][0] = __expf(sc[nt][0] - mn0);
            sc[nt][1] = __expf(sc[nt][1] - mn0);
            sc[nt][2] = __expf(sc[nt][2] - mn1);
            sc[nt][3] = __expf(sc[nt][3] - mn1);
            sum0 += sc[nt][0] + sc[nt][1];
            sum1 += sc[nt][2] + sc[nt][3];
            o[nt][0] *= s0; o[nt][1] *= s0;
            o[nt][2] *= s1; o[nt][3] *= s1;
        }
        sum0 += __shfl_xor_sync(0xffffffffu, sum0, 1);
        sum0 += __shfl_xor_sync(0xffffffffu, sum0, 2);
        sum1 += __shfl_xor_sync(0xffffffffu, sum1, 1);
        sum1 += __shfl_xor_sync(0xffffffffu, sum1, 2);
        l0 = l0 * s0 + sum0;
        l1 = l1 * s1 + sum1;

        // ---- O += P V ----
#pragma unroll
        for (int kk = 0; kk < 4; kk++) {
            uint32_t ph[4];
            ph[0] = packh(sc[2*kk][0],   sc[2*kk][1]);
            ph[1] = packh(sc[2*kk][2],   sc[2*kk][3]);
            ph[2] = packh(sc[2*kk+1][0], sc[2*kk+1][1]);
            ph[3] = packh(sc[2*kk+1][2], sc[2*kk+1][3]);

            uint32_t vh[8][2];
#pragma unroll
            for (int np = 0; np < 4; np++) {
                int krow = kk * 16 + (i4 & 1) * 8 + r8;
                int ncol = np * 16 + (i4 >> 1) * 8;
                uint32_t vr = kv + 2 * AKT + (krow * AL + ncol) * 2;
                uint32_t r0, r1, r2, r3;
                ldsm4t(r0, r1, r2, r3, vr);
                vh[2*np][0] = r0; vh[2*np][1] = r1;
                vh[2*np+1][0] = r2; vh[2*np+1][1] = r3;
            }
#pragma unroll
            for (int nt = 0; nt < 8; nt++)
                mma16816(o[nt], ph, vh[nt]);
        }
        __syncthreads();
    }

    // epilogue: blend with w*PV (Min) and emit fp16
    const float wgt = 1.f - g_w;
    const float i0 = wgt / l0, i1 = wgt / l1;
    const size_t row0 = tokQ + w * 16 + g;
    const size_t base0 = row0 * D_ + h * HC_;
    const size_t base1 = (row0 + 8) * D_ + h * HC_;
#pragma unroll
    for (int nt = 0; nt < 8; nt++) {
        const int cofs = nt * 8 + tg * 2;
        float2 pv0 = *(const float2*)(Min + base0 + cofs);
        float2 pv1 = *(const float2*)(Min + base1 + cofs);
        float v00 = pv0.x + o[nt][0] * i0;
        float v01 = pv0.y + o[nt][1] * i0;
        float v10 = pv1.x + o[nt][2] * i1;
        float v11 = pv1.y + o[nt][3] * i1;
        *(uint32_t*)(Mh + base0 + cofs) = packh(v00, v01);
        *(uint32_t*)(Mh + base1 + cofs) = packh(v10, v11);
    }
}

// ---------------------------------------------------------------------------
// Output projection NT GEMM, single-term: out = Mh(fp16) @ Wf1(fp16)^T + bf
// ---------------------------------------------------------------------------
constexpr int GBUF1 = 2 * GTB;
constexpr int GSMEM1 = 2 * GBUF1;          // 40960

__global__ void __launch_bounds__(256)
out_gemm(const h16* __restrict__ Ah, const h16* __restrict__ Bs,
         const float* __restrict__ bias, float* __restrict__ Cf)
{
    extern __shared__ char sm[];
    const uint32_t su = smem_u32(sm);
    const int tid = threadIdx.x;
    const int wid = tid >> 5, lane = tid & 31;
    const int wm = wid & 1, wn = wid >> 1;
    const int m0 = blockIdx.x * 128, n0 = blockIdx.y * 128;

    const h16* srcs[2] = { Ah + (size_t)m0 * D_, Bs + (size_t)n0 * D_ };

    const int lrow = lane & 15, lcol8 = (lane >> 4) * 8;
    const int g = lane >> 2, tg = lane & 3;

    auto load_chunk = [&](int c, int buf) {
        const int k0 = c * 32;
#pragma unroll
        for (int t = 0; t < 2; t++)
#pragma unroll
            for (int r = 0; r < 2; r++) {
                int id = r * 256 + tid;
                int row = id >> 2, q = id & 3;
                CP16(su + buf * GBUF1 + t * GTB + row * 80 + q * 16,
                     srcs[t] + (size_t)row * D_ + k0 + q * 8);
            }
    };

    load_chunk(0, 0); CP_COMMIT();

    float acc[4][4][4] = {};

    for (int c = 0; c < 32; c++) {
        if (c < 31) { load_chunk(c + 1, (c + 1) & 1); CP_COMMIT(); CP_WAIT(1); }
        else        { CP_WAIT(0); }
        __syncthreads();
        const uint32_t base = su + (c & 1) * GBUF1;
#pragma unroll
        for (int k2 = 0; k2 < 2; k2++) {
            const int kc = k2 * 16 + lcol8;
            uint32_t ah[4][4];
#pragma unroll
            for (int mt = 0; mt < 4; mt++) {
                uint32_t ar = base + ((wm * 64 + mt * 16 + lrow) * GL + kc) * 2;
                ldsm4(ah[mt][0], ah[mt][1], ah[mt][2], ah[mt][3], ar);
            }
            uint32_t bh[4][2];
#pragma unroll
            for (int np = 0; np < 2; np++) {
                uint32_t br = base + GTB + ((wn * 32 + np * 16 + lrow) * GL + kc) * 2;
                uint32_t r0, r1, r2, r3;
                ldsm4(r0, r1, r2, r3, br);
                bh[2*np][0] = r0; bh[2*np][1] = r2;
                bh[2*np+1][0] = r1; bh[2*np+1][1] = r3;
            }
#pragma unroll
            for (int mt = 0; mt < 4; mt++)
#pragma unroll
                for (int nt = 0; nt < 4; nt++)
                    mma16816(acc[mt][nt], ah[mt], bh[nt]);
        }
        __syncthreads();
    }

#pragma unroll
    for (int mt = 0; mt < 4; mt++)
#pragma unroll
        for (int nt = 0; nt < 4; nt++) {
            const int col = n0 + wn * 32 + nt * 8 + tg * 2;
            const float b0v = bias[col], b1v = bias[col + 1];
#pragma unroll
            for (int hf = 0; hf < 2; hf++) {
                const int row = m0 + wm * 64 + mt * 16 + g + hf * 8;
                float2 o;
                o.x = acc[mt][nt][hf * 2]     + b0v;
                o.y = acc[mt][nt][hf * 2 + 1] + b1v;
                *(float2*)(Cf + (size_t)row * D_ + col) = o;
            }
        }
}

// ---------------------------------------------------------------------------
// Launch
// ---------------------------------------------------------------------------
extern "C" void kernel_launch(void* const* d_in, const int* in_sizes, int n_in,
                              void* d_out, int out_size)
{
    const float* x   = (const float*)d_in[0];
    const float* mu  = (const float*)d_in[1];
    const float* lam = (const float*)d_in[2];
    const float* g1  = (const float*)d_in[3];
    const float* g2  = (const float*)d_in[4];
    const float* t1  = (const float*)d_in[5];
    const float* t2  = (const float*)d_in[6];
    const float* Wq  = (const float*)d_in[7];
    const float* bq  = (const float*)d_in[8];
    const float* Wk  = (const float*)d_in[9];
    const float* bk  = (const float*)d_in[10];
    const float* Wv  = (const float*)d_in[11];
    const float* bv  = (const float*)d_in[12];
    const float* Wf  = (const float*)d_in[13];
    const float* bf  = (const float*)d_in[14];
    float* out = (float*)d_out;

    float *Vb, *Mb, *PREb, *partb;
    cudaGetSymbolAddress((void**)&Vb,    g_V);
    cudaGetSymbolAddress((void**)&Mb,    g_M);
    cudaGetSymbolAddress((void**)&PREb,  g_PRE);
    cudaGetSymbolAddress((void**)&partb, g_part);
    h16 *xh, *xl, *Mh, *Wh, *Wl, *Wf1, *Qh, *Ql, *Kh, *Kl, *V1;
    cudaGetSymbolAddress((void**)&xh,  g_xh);
    cudaGetSymbolAddress((void**)&xl,  g_xl);
    cudaGetSymbolAddress((void**)&Mh,  g_Mh);
    cudaGetSymbolAddress((void**)&Wh,  g_Wh);
    cudaGetSymbolAddress((void**)&Wl,  g_Wl);
    cudaGetSymbolAddress((void**)&Wf1, g_Wf1);
    cudaGetSymbolAddress((void**)&Qh,  g_Qh);
    cudaGetSymbolAddress((void**)&Ql,  g_Ql);
    cudaGetSymbolAddress((void**)&Kh,  g_Kh);
    cudaGetSymbolAddress((void**)&Kl,  g_Kl);
    cudaGetSymbolAddress((void**)&V1,  g_V1);

    cudaFuncSetAttribute(qkv_gemm,
                         cudaFuncAttributeMaxDynamicSharedMemorySize, GSMEM3);
    cudaFuncSetAttribute(out_gemm,
                         cudaFuncAttributeMaxDynamicSharedMemorySize, GSMEM1);
    cudaFuncSetAttribute(attn_mma,
                         cudaFuncAttributeMaxDynamicSharedMemorySize, ASM);
    cudaFuncSetAttribute(pwin2,
                         cudaFuncAttributeMaxDynamicSharedMemorySize, PWSMEM);

    const size_t WN = (size_t)D_ * D_;
    const int n4x = NTOK_ * D_ / 4, n4w = (int)(WN / 4);

    // 0: x split + setup table
    split_x_setup<<<(n4x + 255) / 256, 256>>>(x, xh, xl, n4x,
                                              mu, lam, g1, g2, t1, t2);
    // 1: Wq/Wk/Wv splits
    wsplit3<<<dim3((n4w + 255) / 256, 3), 256>>>(Wq, Wk, Wv, Wh, Wl, n4w);
    // 2: Wf fp16
    wsplitF<<<(n4w + 255) / 256, 256>>>(Wf, Wf1, n4w);

    // 3: fused QKV projections (profiled by ncu -s 5)
    dim3 tg(NTOK_ / 128, D_ / 128, 3);
    qkv_gemm<<<tg, 256, GSMEM3>>>(xh, xl,
                                  Wh + 0 * WN, Wl + 0 * WN,
                                  Wh + 1 * WN, Wl + 1 * WN,
                                  Wh + 2 * WN, Wl + 2 * WN,
                                  bq, bk, bv,
                                  Qh, Ql, Kh, Kl, Vb, V1);

    // 4-5: prefix sums
    prefA<<<256, 256>>>(Vb, partb);
    prefC<<<256, 256>>>(Vb, partb, PREb);

    // 6: P-window conv -> M = w*PV
    dim3 pgrid(T_ / 128, NH_, B_);
    pwin2<<<pgrid, 256, PWSMEM>>>(Vb, PREb, Mb);

    // 7: attention (+ blend + fp16 emit)
    dim3 agrid(T_ / 128, NH_, B_);
    attn_mma<<<agrid, 256, ASM>>>(Qh, Ql, Kh, Kl, V1, Mb, Mh);

    // 8: output projection (single term)
    dim3 og(NTOK_ / 128, D_ / 128);
    out_gemm<<<og, 256, GSMEM1>>>(Mh, Wf1, bf, out);
}

// round 7
// speedup vs baseline: 4.2903x; 1.1163x over previous
#include <cuda_runtime.h>
#include <cuda_fp16.h>
#include <math.h>
#include <cstdint>

using h16 = __half;

// ---------------------------------------------------------------------------
// Shapes
// ---------------------------------------------------------------------------
constexpr int B_    = 4;
constexpr int T_    = 2048;
constexpr int D_    = 1024;
constexpr int NH_   = 16;
constexpr int HC_   = 64;
constexpr int NTOK_ = B_ * T_;      // 8192

// ---------------------------------------------------------------------------
// Scratch (device globals)
// ---------------------------------------------------------------------------
__device__ float g_V  [(size_t)NTOK_ * D_];
__device__ float g_M  [(size_t)NTOK_ * D_];   // w * (P@V), consumed by attn
__device__ float g_PRE[(size_t)NTOK_ * D_];
__device__ float g_part[4 * 16 * 1024];
__device__ float g_f[NH_][101];
__device__ float g_w;

__device__ h16 g_xh[(size_t)NTOK_ * D_];
__device__ h16 g_xl[(size_t)NTOK_ * D_];
__device__ h16 g_Mh[(size_t)NTOK_ * D_];      // fp16 blended M (single term)
__device__ h16 g_Wh[3][(size_t)D_ * D_];
__device__ h16 g_Wl[3][(size_t)D_ * D_];
__device__ h16 g_Wf1[(size_t)D_ * D_];
__device__ h16 g_Qh[(size_t)NTOK_ * D_];
__device__ h16 g_Ql[(size_t)NTOK_ * D_];
__device__ h16 g_Kh[(size_t)NTOK_ * D_];
__device__ h16 g_Kl[(size_t)NTOK_ * D_];
__device__ h16 g_V1[(size_t)NTOK_ * D_];

// ---------------------------------------------------------------------------
// PTX helpers
// ---------------------------------------------------------------------------
__device__ __forceinline__ uint32_t smem_u32(const void* p) {
    uint32_t a;
    asm("{ .reg .u64 t; cvta.to.shared.u64 t, %1; cvt.u32.u64 %0, t; }"
        : "=r"(a) : "l"(p));
    return a;
}
#define CP16(s, g) \
    asm volatile("cp.async.cg.shared.global [%0], [%1], 16;" \
                 :: "r"(s), "l"(g) : "memory")
#define CP_COMMIT() asm volatile("cp.async.commit_group;" ::: "memory")
#define CP_WAIT(n)  asm volatile("cp.async.wait_group %0;" :: "n"(n) : "memory")

__device__ __forceinline__ void ldsm4(uint32_t& r0, uint32_t& r1,
                                      uint32_t& r2, uint32_t& r3, uint32_t a) {
    asm volatile("ldmatrix.sync.aligned.m8n8.x4.shared.b16 {%0,%1,%2,%3}, [%4];"
                 : "=r"(r0), "=r"(r1), "=r"(r2), "=r"(r3) : "r"(a));
}
__device__ __forceinline__ void ldsm4t(uint32_t& r0, uint32_t& r1,
                                       uint32_t& r2, uint32_t& r3, uint32_t a) {
    asm volatile("ldmatrix.sync.aligned.m8n8.x4.trans.shared.b16 {%0,%1,%2,%3}, [%4];"
                 : "=r"(r0), "=r"(r1), "=r"(r2), "=r"(r3) : "r"(a));
}
__device__ __forceinline__ void mma16816(float* c, const uint32_t* a, const uint32_t* b) {
    asm volatile(
        "mma.sync.aligned.m16n8k16.row.col.f32.f16.f16.f32 "
        "{%0,%1,%2,%3},{%4,%5,%6,%7},{%8,%9},{%0,%1,%2,%3};"
        : "+f"(c[0]), "+f"(c[1]), "+f"(c[2]), "+f"(c[3])
        : "r"(a[0]), "r"(a[1]), "r"(a[2]), "r"(a[3]), "r"(b[0]), "r"(b[1]));
}
__device__ __forceinline__ uint32_t packh(float lo, float hi) {
    uint32_t r;
    asm("cvt.rn.f16x2.f32 %0, %1, %2;" : "=r"(r) : "f"(hi), "f"(lo));
    return r;
}

// ---------------------------------------------------------------------------
// Launch 0: split x into fp16 hi/lo; block 0 additionally builds g_f / g_w
// ---------------------------------------------------------------------------
__global__ void split_x_setup(const float* __restrict__ s,
                              h16* __restrict__ hi, h16* __restrict__ lo, int n4,
                              const float* __restrict__ mu,
                              const float* __restrict__ lam,
                              const float* __restrict__ g1,
                              const float* __restrict__ g2,
                              const float* __restrict__ t1,
                              const float* __restrict__ t2)
{
    if (blockIdx.x == 0) {
        int tid = threadIdx.x;
        if (tid == 0) g_w = 1.f / (1.f + expf(-mu[0]));
        for (int idx = tid; idx < NH_ * 101; idx += blockDim.x) {
            int h = idx / 101, L = idx % 101;
            float Lf = (float)L;
            float val;
            if (h < 4) {
                float base = lam[h];
                float mag  = expf(Lf * logf(fabsf(base)));
                float sgn  = (base < 0.f) ? (1.f - 2.f * (float)(L & 1)) : 1.f;
                val = mag * sgn;
            } else if (h < 10) {
                int s2 = h - 4;
                val = expf(Lf * logf(g1[s2])) * sinf(t1[s2] * Lf);
            } else {
                int s2 = h - 10;
                val = expf(Lf * logf(g2[s2])) * cosf(t2[s2] * Lf);
            }
            g_f[h][L] = val;
        }
    }
    int i = blockIdx.x * blockDim.x + threadIdx.x;
    if (i >= n4) return;
    float4 a = ((const float4*)s)[i];
    float h0 = __half2float(__float2half_rn(a.x));
    float h1 = __half2float(__float2half_rn(a.y));
    float h2 = __half2float(__float2half_rn(a.z));
    float h3 = __half2float(__float2half_rn(a.w));
    uint2 H, L;
    H.x = packh(a.x, a.y);            H.y = packh(a.z, a.w);
    L.x = packh(a.x - h0, a.y - h1);  L.y = packh(a.z - h2, a.w - h3);
    ((uint2*)hi)[i] = H;
    ((uint2*)lo)[i] = L;
}

// ---------------------------------------------------------------------------
// Launch 1: Wq/Wk/Wv hi/lo splits
// ---------------------------------------------------------------------------
__global__ void wsplit3(const float* __restrict__ Wq, const float* __restrict__ Wk,
                        const float* __restrict__ Wv,
                        h16* __restrict__ Wh, h16* __restrict__ Wl, int n4)
{
    int i = blockIdx.x * blockDim.x + threadIdx.x;
    if (i >= n4) return;
    const int z = blockIdx.y;
    const float* src = (z == 0) ? Wq : (z == 1) ? Wk : Wv;
    float4 a = ((const float4*)src)[i];
    const size_t WN = (size_t)D_ * D_;
    float h0 = __half2float(__float2half_rn(a.x));
    float h1 = __half2float(__float2half_rn(a.y));
    float h2 = __half2float(__float2half_rn(a.z));
    float h3 = __half2float(__float2half_rn(a.w));
    uint2 H, L;
    H.x = packh(a.x, a.y);            H.y = packh(a.z, a.w);
    L.x = packh(a.x - h0, a.y - h1);  L.y = packh(a.z - h2, a.w - h3);
    ((uint2*)(Wh + z * WN))[i] = H;
    ((uint2*)(Wl + z * WN))[i] = L;
}

// ---------------------------------------------------------------------------
// Launch 2: Wf -> single fp16
// ---------------------------------------------------------------------------
__global__ void wsplitF(const float* __restrict__ Wf, h16* __restrict__ Wf1, int n4)
{
    int i = blockIdx.x * blockDim.x + threadIdx.x;
    if (i >= n4) return;
    float4 a = ((const float4*)Wf)[i];
    uint2 H;
    H.x = packh(a.x, a.y);  H.y = packh(a.z, a.w);
    ((uint2*)Wf1)[i] = H;
}

// ---------------------------------------------------------------------------
// Launch 3 (PROFILED): fused QKV NT GEMM, 3-stage cp.async, swizzled smem
// Tiles: 128 rows x 32 halves (64 B/row). Swizzle key (row>>1)&3 on 16B chunks.
// Stage = xh, xl, Bh, Bl (8192 B each) = 32768 B; 3 stages = 98304 B.
// ---------------------------------------------------------------------------
constexpr int QT_TILE  = 8192;
constexpr int QT_STAGE = 4 * QT_TILE;      // 32768
constexpr int QT_SMEM  = 3 * QT_STAGE;     // 98304

__global__ void __launch_bounds__(256, 2)
qkv_gemm(const h16* __restrict__ xh, const h16* __restrict__ xl,
         const h16* __restrict__ W0h, const h16* __restrict__ W0l,
         const h16* __restrict__ W1h, const h16* __restrict__ W1l,
         const h16* __restrict__ W2h, const h16* __restrict__ W2l,
         const float* __restrict__ b0, const float* __restrict__ b1,
         const float* __restrict__ b2,
         h16* __restrict__ Qh, h16* __restrict__ Ql,
         h16* __restrict__ Kh, h16* __restrict__ Kl,
         float* __restrict__ Vf, h16* __restrict__ V1)
{
    extern __shared__ char sm[];
    const uint32_t su = smem_u32(sm);
    const int tid = threadIdx.x;
    const int wid = tid >> 5, lane = tid & 31;
    const int wm = wid & 1, wn = wid >> 1;
    const int m0 = blockIdx.x * 128, n0 = blockIdx.y * 128;
    const int z = blockIdx.z;
    const bool isV = (z == 2);

    const h16* Bh = (z == 0) ? W0h : (z == 1) ? W1h : W2h;
    const h16* Bl = (z == 0) ? W0l : (z == 1) ? W1l : W2l;
    const float* bias = (z == 0) ? b0 : (z == 1) ? b1 : b2;

    const h16* srcs[4] = { xh + (size_t)m0 * D_, xl + (size_t)m0 * D_,
                           Bh + (size_t)n0 * D_, Bl + (size_t)n0 * D_ };

    const int lrow = lane & 15, lc16 = lane >> 4;   // 16B chunk half
    const int g = lane >> 2, tg = lane & 3;

    auto load_stage = [&](int c, int st) {
        const int k0 = c * 32;
        const uint32_t sb = su + st * QT_STAGE;
#pragma unroll
        for (int t = 0; t < 4; t++)
#pragma unroll
            for (int r = 0; r < 2; r++) {
                int id = r * 256 + tid;
                int row = id >> 2, q = id & 3;
                uint32_t dst = sb + t * QT_TILE + row * 64
                             + ((q ^ ((row >> 1) & 3)) << 4);
                CP16(dst, srcs[t] + (size_t)row * D_ + k0 + q * 8);
            }
    };

    load_stage(0, 0); CP_COMMIT();
    load_stage(1, 1); CP_COMMIT();

    float acc[4][4][4] = {};
    int st = 0;
    const int NCH = 32;
    for (int c = 0; c < NCH; c++) {
        if (c < NCH - 1) { CP_WAIT(1); } else { CP_WAIT(0); }
        __syncthreads();
        if (c + 2 < NCH) {
            int wst = st + 2; if (wst >= 3) wst -= 3;
            load_stage(c + 2, wst); CP_COMMIT();
        }
        const uint32_t base = su + st * QT_STAGE;
#pragma unroll
        for (int k2 = 0; k2 < 2; k2++) {
            const int cc = k2 * 2 + lc16;
            uint32_t ah[4][4], al[4][4];
#pragma unroll
            for (int mt = 0; mt < 4; mt++) {
                int row = wm * 64 + mt * 16 + lrow;
                uint32_t ar = base + row * 64 + ((cc ^ ((row >> 1) & 3)) << 4);
                ldsm4(ah[mt][0], ah[mt][1], ah[mt][2], ah[mt][3], ar);
                ldsm4(al[mt][0], al[mt][1], al[mt][2], al[mt][3], ar + QT_TILE);
            }
            uint32_t bh[4][2], bl[4][2];
#pragma unroll
            for (int np = 0; np < 2; np++) {
                int row = wn * 32 + np * 16 + lrow;
                uint32_t br = base + 2 * QT_TILE + row * 64
                            + ((cc ^ ((row >> 1) & 3)) << 4);
                uint32_t r0, r1, r2, r3;
                ldsm4(r0, r1, r2, r3, br);
                bh[2*np][0] = r0; bh[2*np][1] = r2;
                bh[2*np+1][0] = r1; bh[2*np+1][1] = r3;
                ldsm4(r0, r1, r2, r3, br + QT_TILE);
                bl[2*np][0] = r0; bl[2*np][1] = r2;
                bl[2*np+1][0] = r1; bl[2*np+1][1] = r3;
            }
#pragma unroll
            for (int mt = 0; mt < 4; mt++)
#pragma unroll
                for (int nt = 0; nt < 4; nt++) {
                    mma16816(acc[mt][nt], ah[mt], bh[nt]);
                    mma16816(acc[mt][nt], ah[mt], bl[nt]);
                }
            if (!isV) {
#pragma unroll
                for (int mt = 0; mt < 4; mt++)
#pragma unroll
                    for (int nt = 0; nt < 4; nt++)
                        mma16816(acc[mt][nt], al[mt], bh[nt]);
            }
        }
        st = (st == 2) ? 0 : st + 1;
    }

    h16* Ch = (z == 0) ? Qh : Kh;
    h16* Cl = (z == 0) ? Ql : Kl;
#pragma unroll
    for (int mt = 0; mt < 4; mt++)
#pragma unroll
        for (int nt = 0; nt < 4; nt++) {
            const int col = n0 + wn * 32 + nt * 8 + tg * 2;
            const float b0v = bias[col], b1v = bias[col + 1];
#pragma unroll
            for (int hf = 0; hf < 2; hf++) {
                const int row = m0 + wm * 64 + mt * 16 + g + hf * 8;
                float v0 = acc[mt][nt][hf * 2]     + b0v;
                float v1 = acc[mt][nt][hf * 2 + 1] + b1v;
                if (isV) {
                    float2 o; o.x = v0; o.y = v1;
                    *(float2*)(Vf + (size_t)row * D_ + col) = o;
                    *(uint32_t*)(V1 + (size_t)row * D_ + col) = packh(v0, v1);
                } else {
                    float h0 = __half2float(__float2half_rn(v0));
                    float h1 = __half2float(__float2half_rn(v1));
                    *(uint32_t*)(Ch + (size_t)row * D_ + col) = packh(v0, v1);
                    *(uint32_t*)(Cl + (size_t)row * D_ + col) = packh(v0 - h0, v1 - h1);
                }
            }
        }
}

// ---------------------------------------------------------------------------
// Parallel prefix sums of V along t
// ---------------------------------------------------------------------------
__global__ void prefA(const float* __restrict__ V, float* __restrict__ part)
{
    int idx = blockIdx.x * blockDim.x + threadIdx.x;
    int d = idx & 1023, seg = (idx >> 10) & 15, b = idx >> 14;
    size_t base = ((size_t)(b * T_) + seg * 128) * D_ + d;
    float s = 0.f;
#pragma unroll 4
    for (int i = 0; i < 128; i++) s += V[base + (size_t)i * D_];
    part[(b * 16 + seg) * 1024 + d] = s;
}

__global__ void prefC(const float* __restrict__ V, const float* __restrict__ part,
                      float* __restrict__ PRE)
{
    int idx = blockIdx.x * blockDim.x + threadIdx.x;
    int d = idx & 1023, seg = (idx >> 10) & 15, b = idx >> 14;
    float off = 0.f;
    for (int s2 = 0; s2 < seg; s2++) off += part[(b * 16 + s2) * 1024 + d];
    size_t base = ((size_t)(b * T_) + seg * 128) * D_ + d;
    float s = off;
#pragma unroll 4
    for (int i = 0; i < 128; i++) {
        s += V[base + (size_t)i * D_];
        PRE[base + (size_t)i * D_] = s;
    }
}

// ---------------------------------------------------------------------------
// P@V window conv: writes M = w * (P@V)
// ---------------------------------------------------------------------------
constexpr int PWS   = 237;
constexpr int PWSMEM = (104 + 64 * PWS) * 4;

__global__ void __launch_bounds__(256)
pwin2(const float* __restrict__ V, const float* __restrict__ PRE,
      float* __restrict__ M)
{
    extern __shared__ float ps[];
    float* fs = ps;
    float* Vs = ps + 104;

    const int tid = threadIdx.x;
    const int t0 = blockIdx.x * 128, h = blockIdx.y, b = blockIdx.z;

    if (tid < 101) fs[tid] = g_f[h][tid];
    for (int id = tid; id < 228 * 16; id += 256) {
        int r = id >> 4, q = id & 15;
        int t = t0 - 100 + r;
        float4 v = make_float4(0.f, 0.f, 0.f, 0.f);
        if (t >= 0)
            v = *(const float4*)(V + ((size_t)(b * T_) + t) * D_ + h * HC_ + q * 4);
        Vs[(q * 4 + 0) * PWS + r] = v.x;
        Vs[(q * 4 + 1) * PWS + r] = v.y;
        Vs[(q * 4 + 2) * PWS + r] = v.z;
        Vs[(q * 4 + 3) * PWS + r] = v.w;
    }
    __syncthreads();

    const int c = tid & 63, tq = tid >> 6;
    const float f100 = fs[100];
    const float wv = g_w;
    const float* vc = Vs + c * PWS;

#pragma unroll 1
    for (int s = 0; s < 8; s++) {
        const int tb = (tq + 4 * s) * 4;
        float a0 = 0.f, a1 = 0.f, a2 = 0.f, a3 = 0.f;
#pragma unroll 4
        for (int j = tb - 99; j <= tb + 2; j++) {
            float v = vc[j + 100];
            int d0 = tb - j;
            if (d0 >= 1 && d0 <= 99)     a0 += fs[d0] * v;
            if (d0 + 1 >= 1 && d0 + 1 <= 99) a1 += fs[d0 + 1] * v;
            if (d0 + 2 >= 1 && d0 + 2 <= 99) a2 += fs[d0 + 2] * v;
            if (d0 + 3 >= 1 && d0 + 3 <= 99) a3 += fs[d0 + 3] * v;
        }
        float acc[4] = { a0, a1, a2, a3 };
#pragma unroll
        for (int i = 0; i < 4; i++) {
            int t = t0 + tb + i;
            float a = acc[i];
            if (t >= 100)
                a += f100 * PRE[((size_t)(b * T_) + t - 100) * D_ + h * HC_ + c];
            M[((size_t)(b * T_) + t) * D_ + h * HC_ + c] = wv * a;
        }
    }
}

// ---------------------------------------------------------------------------
// HMMA flash attention, 3-stage cp.async, swizzled smem (128B rows, key row&7)
// Q hi/lo resident (16384 B each); stage = Kh, Kl, V1 (8192 each) = 24576 B.
// SMEM = 32768 + 3*24576 = 106496 B.
// ---------------------------------------------------------------------------
constexpr int AQTILE = 16384;
constexpr int AKTILE = 8192;
constexpr int ASTAGE = 3 * AKTILE;         // 24576
constexpr int ASMEMN = 2 * AQTILE + 3 * ASTAGE;   // 106496

__global__ void __launch_bounds__(256, 2)
attn_mma(const h16* __restrict__ Qh, const h16* __restrict__ Ql,
         const h16* __restrict__ Kh, const h16* __restrict__ Kl,
         const h16* __restrict__ V1, const float* __restrict__ Min,
         h16* __restrict__ Mh)
{
    extern __shared__ char sm[];
    const uint32_t su = smem_u32(sm);
    const int tid = threadIdx.x;
    const int w = tid >> 5, lane = tid & 31;
    const int b = blockIdx.z, h = blockIdx.y, qt = blockIdx.x;
    const size_t tokQ = (size_t)b * T_ + qt * 128;
    const int lrow = lane & 15, lc16 = lane >> 4;
    const int g = lane >> 2, tg = lane & 3;
    const int i4 = lane >> 3, r8 = lane & 7;

    // Q tiles (hi, lo) swizzled — in cp.async group 0 together with stage 0
    {
        const h16* qs[2] = { Qh, Ql };
#pragma unroll
        for (int t = 0; t < 2; t++)
#pragma unroll
            for (int r = 0; r < 4; r++) {
                int id = r * 256 + tid;
                int row = id >> 3, q = id & 7;
                uint32_t dst = su + t * AQTILE + row * 128 + ((q ^ (row & 7)) << 4);
                CP16(dst, qs[t] + (tokQ + row) * D_ + h * HC_ + q * 8);
            }
    }
    const h16* kvs[3] = { Kh, Kl, V1 };
    auto load_stage = [&](int kt, int stg) {
        const size_t tok = (size_t)b * T_ + kt * 64;
        const uint32_t sb = su + 2 * AQTILE + stg * ASTAGE;
#pragma unroll
        for (int t = 0; t < 3; t++)
#pragma unroll
            for (int r = 0; r < 2; r++) {
                int id = r * 256 + tid;
                int row = id >> 3, q = id & 7;
                uint32_t dst = sb + t * AKTILE + row * 128 + ((q ^ (row & 7)) << 4);
                CP16(dst, kvs[t] + (tok + row) * D_ + h * HC_ + q * 8);
            }
    };
    load_stage(0, 0); CP_COMMIT();
    load_stage(1, 1); CP_COMMIT();

    float o[8][4] = {};
    float m0r = -1e30f, m1r = -1e30f, l0 = 0.f, l1 = 0.f;

    const int NKT = T_ / 64;   // 32
    int stg = 0;
    for (int kt = 0; kt < NKT; kt++) {
        if (kt < NKT - 1) { CP_WAIT(1); } else { CP_WAIT(0); }
        __syncthreads();
        if (kt + 2 < NKT) {
            int wst = stg + 2; if (wst >= 3) wst -= 3;
            load_stage(kt + 2, wst); CP_COMMIT();
        }
        const uint32_t kv = su + 2 * AQTILE + stg * ASTAGE;

        // ---- S = Q K^T (3-term fp16 split) ----
        float sc[8][4] = {};
#pragma unroll
        for (int kk = 0; kk < 4; kk++) {
            const int cc = kk * 2 + lc16;
            uint32_t aq[4], aql[4];
            {
                int row = w * 16 + lrow;
                uint32_t ar = su + row * 128 + ((cc ^ (row & 7)) << 4);
                ldsm4(aq[0], aq[1], aq[2], aq[3], ar);
                ldsm4(aql[0], aql[1], aql[2], aql[3], ar + AQTILE);
            }
            uint32_t bh[8][2], bl[8][2];
#pragma unroll
            for (int np = 0; np < 4; np++) {
                int row = np * 16 + lrow;
                uint32_t br = kv + row * 128 + ((cc ^ (row & 7)) << 4);
                uint32_t r0, r1, r2, r3;
                ldsm4(r0, r1, r2, r3, br);
                bh[2*np][0] = r0; bh[2*np][1] = r2;
                bh[2*np+1][0] = r1; bh[2*np+1][1] = r3;
                ldsm4(r0, r1, r2, r3, br + AKTILE);
                bl[2*np][0] = r0; bl[2*np][1] = r2;
                bl[2*np+1][0] = r1; bl[2*np+1][1] = r3;
            }
#pragma unroll
            for (int nt = 0; nt < 8; nt++) {
                mma16816(sc[nt], aq, bh[nt]);
                mma16816(sc[nt], aq, bl[nt]);
                mma16816(sc[nt], aql, bh[nt]);
            }
        }

        // ---- online softmax ----
        float mx0 = -1e30f, mx1 = -1e30f;
#pragma unroll
        for (int nt = 0; nt < 8; nt++) {
            mx0 = fmaxf(mx0, fmaxf(sc[nt][0], sc[nt][1]));
            mx1 = fmaxf(mx1, fmaxf(sc[nt][2], sc[nt][3]));
        }
        mx0 = fmaxf(mx0, __shfl_xor_sync(0xffffffffu, mx0, 1));
        mx0 = fmaxf(mx0, __shfl_xor_sync(0xffffffffu, mx0, 2));
        mx1 = fmaxf(mx1, __shfl_xor_sync(0xffffffffu, mx1, 1));
        mx1 = fmaxf(mx1, __shfl_xor_sync(0xffffffffu, mx1, 2));
        const float mn0 = fmaxf(m0r, mx0), mn1 = fmaxf(m1r, mx1);
        const float s0 = __expf(m0r - mn0), s1 = __expf(m1r - mn1);
        m0r = mn0; m1r = mn1;
        float sum0 = 0.f, sum1 = 0.f;
#pragma unroll
        for (int nt = 0; nt < 8; nt++) {
            sc[nt][0] = __expf(sc[nt][0] - mn0);
            sc[nt][1] = __expf(sc[nt][1] - mn0);
            sc[nt][2] = __expf(sc[nt][2] - mn1);
            sc[nt][3] = __expf(sc[nt][3] - mn1);
            sum0 += sc[nt][0] + sc[nt][1];
            sum1 += sc[nt][2] + sc[nt][3];
            o[nt][0] *= s0; o[nt][1] *= s0;
            o[nt][2] *= s1; o[nt][3] *= s1;
        }
        sum0 += __shfl_xor_sync(0xffffffffu, sum0, 1);
        sum0 += __shfl_xor_sync(0xffffffffu, sum0, 2);
        sum1 += __shfl_xor_sync(0xffffffffu, sum1, 1);
        sum1 += __shfl_xor_sync(0xffffffffu, sum1, 2);
        l0 = l0 * s0 + sum0;
        l1 = l1 * s1 + sum1;

        // ---- O += P V ----
#pragma unroll
        for (int kk = 0; kk < 4; kk++) {
            uint32_t ph[4];
            ph[0] = packh(sc[2*kk][0],   sc[2*kk][1]);
            ph[1] = packh(sc[2*kk][2],   sc[2*kk][3]);
            ph[2] = packh(sc[2*kk+1][0], sc[2*kk+1][1]);
            ph[3] = packh(sc[2*kk+1][2], sc[2*kk+1][3]);

            uint32_t vh[8][2];
#pragma unroll
            for (int np = 0; np < 4; np++) {
                int krow = kk * 16 + (i4 & 1) * 8 + r8;
                int cc = np * 2 + (i4 >> 1);
                uint32_t vr = kv + 2 * AKTILE + krow * 128 + ((cc ^ (krow & 7)) << 4);
                uint32_t r0, r1, r2, r3;
                ldsm4t(r0, r1, r2, r3, vr);
                vh[2*np][0] = r0; vh[2*np][1] = r1;
                vh[2*np+1][0] = r2; vh[2*np+1][1] = r3;
            }
#pragma unroll
            for (int nt = 0; nt < 8; nt++)
                mma16816(o[nt], ph, vh[nt]);
        }
        stg = (stg == 2) ? 0 : stg + 1;
    }

    // epilogue: blend with w*PV (Min) and emit fp16
    const float wgt = 1.f - g_w;
    const float i0 = wgt / l0, i1 = wgt / l1;
    const size_t row0 = tokQ + w * 16 + g;
    const size_t base0 = row0 * D_ + h * HC_;
    const size_t base1 = (row0 + 8) * D_ + h * HC_;
#pragma unroll
    for (int nt = 0; nt < 8; nt++) {
        const int cofs = nt * 8 + tg * 2;
        float2 pv0 = *(const float2*)(Min + base0 + cofs);
        float2 pv1 = *(const float2*)(Min + base1 + cofs);
        float v00 = pv0.x + o[nt][0] * i0;
        float v01 = pv0.y + o[nt][1] * i0;
        float v10 = pv1.x + o[nt][2] * i1;
        float v11 = pv1.y + o[nt][3] * i1;
        *(uint32_t*)(Mh + base0 + cofs) = packh(v00, v01);
        *(uint32_t*)(Mh + base1 + cofs) = packh(v10, v11);
    }
}

// ---------------------------------------------------------------------------
// Output projection NT GEMM, single-term, 3-stage swizzled
// ---------------------------------------------------------------------------
constexpr int OT_STAGE = 2 * QT_TILE;      // 16384
constexpr int OT_SMEM  = 3 * OT_STAGE;     // 49152

__global__ void __launch_bounds__(256, 2)
out_gemm(const h16* __restrict__ Ah, const h16* __restrict__ Bs,
         const float* __restrict__ bias, float* __restrict__ Cf)
{
    extern __shared__ char sm[];
    const uint32_t su = smem_u32(sm);
    const int tid = threadIdx.x;
    const int wid = tid >> 5, lane = tid & 31;
    const int wm = wid & 1, wn = wid >> 1;
    const int m0 = blockIdx.x * 128, n0 = blockIdx.y * 128;

    const h16* srcs[2] = { Ah + (size_t)m0 * D_, Bs + (size_t)n0 * D_ };

    const int lrow = lane & 15, lc16 = lane >> 4;
    const int g = lane >> 2, tg = lane & 3;

    auto load_stage = [&](int c, int st) {
        const int k0 = c * 32;
        const uint32_t sb = su + st * OT_STAGE;
#pragma unroll
        for (int t = 0; t < 2; t++)
#pragma unroll
            for (int r = 0; r < 2; r++) {
                int id = r * 256 + tid;
                int row = id >> 2, q = id & 3;
                uint32_t dst = sb + t * QT_TILE + row * 64
                             + ((q ^ ((row >> 1) & 3)) << 4);
                CP16(dst, srcs[t] + (size_t)row * D_ + k0 + q * 8);
            }
    };

    load_stage(0, 0); CP_COMMIT();
    load_stage(1, 1); CP_COMMIT();

    float acc[4][4][4] = {};
    int st = 0;
    const int NCH = 32;
    for (int c = 0; c < NCH; c++) {
        if (c < NCH - 1) { CP_WAIT(1); } else { CP_WAIT(0); }
        __syncthreads();
        if (c + 2 < NCH) {
            int wst = st + 2; if (wst >= 3) wst -= 3;
            load_stage(c + 2, wst); CP_COMMIT();
        }
        const uint32_t base = su + st * OT_STAGE;
#pragma unroll
        for (int k2 = 0; k2 < 2; k2++) {
            const int cc = k2 * 2 + lc16;
            uint32_t ah[4][4];
#pragma unroll
            for (int mt = 0; mt < 4; mt++) {
                int row = wm * 64 + mt * 16 + lrow;
                uint32_t ar = base + row * 64 + ((cc ^ ((row >> 1) & 3)) << 4);
                ldsm4(ah[mt][0], ah[mt][1], ah[mt][2], ah[mt][3], ar);
            }
            uint32_t bh[4][2];
#pragma unroll
            for (int np = 0; np < 2; np++) {
                int row = wn * 32 + np * 16 + lrow;
                uint32_t br = base + QT_TILE + row * 64
                            + ((cc ^ ((row >> 1) & 3)) << 4);
                uint32_t r0, r1, r2, r3;
                ldsm4(r0, r1, r2, r3, br);
                bh[2*np][0] = r0; bh[2*np][1] = r2;
                bh[2*np+1][0] = r1; bh[2*np+1][1] = r3;
            }
#pragma unroll
            for (int mt = 0; mt < 4; mt++)
#pragma unroll
                for (int nt = 0; nt < 4; nt++)
                    mma16816(acc[mt][nt], ah[mt], bh[nt]);
        }
        st = (st == 2) ? 0 : st + 1;
    }

#pragma unroll
    for (int mt = 0; mt < 4; mt++)
#pragma unroll
        for (int nt = 0; nt < 4; nt++) {
            const int col = n0 + wn * 32 + nt * 8 + tg * 2;
            const float b0v = bias[col], b1v = bias[col + 1];
#pragma unroll
            for (int hf = 0; hf < 2; hf++) {
                const int row = m0 + wm * 64 + mt * 16 + g + hf * 8;
                float2 o;
                o.x = acc[mt][nt][hf * 2]     + b0v;
                o.y = acc[mt][nt][hf * 2 + 1] + b1v;
                *(float2*)(Cf + (size_t)row * D_ + col) = o;
            }
        }
}

// ---------------------------------------------------------------------------
// Launch
// ---------------------------------------------------------------------------
extern "C" void kernel_launch(void* const* d_in, const int* in_sizes, int n_in,
                              void* d_out, int out_size)
{
    const float* x   = (const float*)d_in[0];
    const float* mu  = (const float*)d_in[1];
    const float* lam = (const float*)d_in[2];
    const float* g1  = (const float*)d_in[3];
    const float* g2  = (const float*)d_in[4];
    const float* t1  = (const float*)d_in[5];
    const float* t2  = (const float*)d_in[6];
    const float* Wq  = (const float*)d_in[7];
    const float* bq  = (const float*)d_in[8];
    const float* Wk  = (const float*)d_in[9];
    const float* bk  = (const float*)d_in[10];
    const float* Wv  = (const float*)d_in[11];
    const float* bv  = (const float*)d_in[12];
    const float* Wf  = (const float*)d_in[13];
    const float* bf  = (const float*)d_in[14];
    float* out = (float*)d_out;

    float *Vb, *Mb, *PREb, *partb;
    cudaGetSymbolAddress((void**)&Vb,    g_V);
    cudaGetSymbolAddress((void**)&Mb,    g_M);
    cudaGetSymbolAddress((void**)&PREb,  g_PRE);
    cudaGetSymbolAddress((void**)&partb, g_part);
    h16 *xh, *xl, *Mh, *Wh, *Wl, *Wf1, *Qh, *Ql, *Kh, *Kl, *V1;
    cudaGetSymbolAddress((void**)&xh,  g_xh);
    cudaGetSymbolAddress((void**)&xl,  g_xl);
    cudaGetSymbolAddress((void**)&Mh,  g_Mh);
    cudaGetSymbolAddress((void**)&Wh,  g_Wh);
    cudaGetSymbolAddress((void**)&Wl,  g_Wl);
    cudaGetSymbolAddress((void**)&Wf1, g_Wf1);
    cudaGetSymbolAddress((void**)&Qh,  g_Qh);
    cudaGetSymbolAddress((void**)&Ql,  g_Ql);
    cudaGetSymbolAddress((void**)&Kh,  g_Kh);
    cudaGetSymbolAddress((void**)&Kl,  g_Kl);
    cudaGetSymbolAddress((void**)&V1,  g_V1);

    cudaFuncSetAttribute(qkv_gemm,
                         cudaFuncAttributeMaxDynamicSharedMemorySize, QT_SMEM);
    cudaFuncSetAttribute(out_gemm,
                         cudaFuncAttributeMaxDynamicSharedMemorySize, OT_SMEM);
    cudaFuncSetAttribute(attn_mma,
                         cudaFuncAttributeMaxDynamicSharedMemorySize, ASMEMN);
    cudaFuncSetAttribute(pwin2,
                         cudaFuncAttributeMaxDynamicSharedMemorySize, PWSMEM);

    const size_t WN = (size_t)D_ * D_;
    const int n4x = NTOK_ * D_ / 4, n4w = (int)(WN / 4);

    // 0: x split + setup table
    split_x_setup<<<(n4x + 255) / 256, 256>>>(x, xh, xl, n4x,
                                              mu, lam, g1, g2, t1, t2);
    // 1: Wq/Wk/Wv splits
    wsplit3<<<dim3((n4w + 255) / 256, 3), 256>>>(Wq, Wk, Wv, Wh, Wl, n4w);
    // 2: Wf fp16
    wsplitF<<<(n4w + 255) / 256, 256>>>(Wf, Wf1, n4w);

    // 3: fused QKV projections (profiled by ncu -s 5)
    dim3 tg(NTOK_ / 128, D_ / 128, 3);
    qkv_gemm<<<tg, 256, QT_SMEM>>>(xh, xl,
                                   Wh + 0 * WN, Wl + 0 * WN,
                                   Wh + 1 * WN, Wl + 1 * WN,
                                   Wh + 2 * WN, Wl + 2 * WN,
                                   bq, bk, bv,
                                   Qh, Ql, Kh, Kl, Vb, V1);

    // 4-5: prefix sums
    prefA<<<256, 256>>>(Vb, partb);
    prefC<<<256, 256>>>(Vb, partb, PREb);

    // 6: P-window conv -> M = w*PV
    dim3 pgrid(T_ / 128, NH_, B_);
    pwin2<<<pgrid, 256, PWSMEM>>>(Vb, PREb, Mb);

    // 7: attention (+ blend + fp16 emit)
    dim3 agrid(T_ / 128, NH_, B_);
    attn_mma<<<agrid, 256, ASMEMN>>>(Qh, Ql, Kh, Kl, V1, Mb, Mh);

    // 8: output projection (single term)
    dim3 og(NTOK_ / 128, D_ / 128);
    out_gemm<<<og, 256, OT_SMEM>>>(Mh, Wf1, bf, out);
}